// round 1
// baseline (speedup 1.0000x reference)
#include <cuda_runtime.h>
#include <math.h>

#define DMODEL 1024
#define NHEADS 8
#define DK 128
#define BB 2
#define SS 2048

// Scratch (allocation-free rule: __device__ globals)
__device__ float g_q[(size_t)BB * SS * DMODEL];
__device__ float g_k[(size_t)BB * SS * DMODEL];
__device__ float g_v[(size_t)BB * SS * DMODEL];
__device__ float g_ctx[(size_t)BB * SS * DMODEL];
__device__ float g_attn_fallback[(size_t)BB * NHEADS * SS * SS];

// ----------------------------------------------------------------------------
// Generic batched SGEMM:  C = alpha * A @ op(B) + bias
//   A: [M,K] row-major, row stride lda
//   TRANS_B: B is [N,K] row-major (computes A @ B^T); else B is [K,N]
//   Batch z decomposed as (zb = z / Hdiv, zh = z % Hdiv), pointer offsets
//   offX = zb*sXb + zh*sXh.
// Tile: 128x128x8, 256 threads, 8x8 per thread.
// All dims here are multiples of the tile (M%128==0, N%128==0, K%8==0).
// ----------------------------------------------------------------------------
template <bool TRANS_B, bool HAS_BIAS>
__global__ __launch_bounds__(256) void gemm_kernel(
    const float* __restrict__ A, const float* __restrict__ B,
    const float* __restrict__ bias, float* __restrict__ C,
    int M, int N, int K, int lda, int ldb, int ldc, float alpha,
    int Hdiv,
    long long sAb, long long sAh,
    long long sBb, long long sBh,
    long long sCb, long long sCh)
{
    const int z  = blockIdx.z;
    const int zb = z / Hdiv;
    const int zh = z % Hdiv;
    A += zb * sAb + zh * sAh;
    B += zb * sBb + zh * sBh;
    C += zb * sCb + zh * sCh;

    __shared__ float As[8][132];  // padded: conflict-free transposed stores
    __shared__ float Bs[8][132];

    const int tid = threadIdx.x;
    const int m0 = blockIdx.y * 128;
    const int n0 = blockIdx.x * 128;

    // A-tile loader mapping: each thread loads one float4 of a 128x8 tile
    const int aRow  = tid >> 1;          // 0..127
    const int aCol4 = (tid & 1) * 4;     // 0 or 4

    // compute mapping
    const int tx = tid & 15;   // n-fragment
    const int ty = tid >> 4;   // m-fragment

    float acc[8][8];
#pragma unroll
    for (int i = 0; i < 8; i++)
#pragma unroll
        for (int j = 0; j < 8; j++) acc[i][j] = 0.0f;

    for (int k0 = 0; k0 < K; k0 += 8) {
        // ---- load A tile (transpose into As[k][m]) ----
        {
            float4 a4 = *reinterpret_cast<const float4*>(
                A + (long long)(m0 + aRow) * lda + k0 + aCol4);
            As[aCol4 + 0][aRow] = a4.x;
            As[aCol4 + 1][aRow] = a4.y;
            As[aCol4 + 2][aRow] = a4.z;
            As[aCol4 + 3][aRow] = a4.w;
        }
        // ---- load B tile ----
        if (TRANS_B) {
            float4 b4 = *reinterpret_cast<const float4*>(
                B + (long long)(n0 + aRow) * ldb + k0 + aCol4);
            Bs[aCol4 + 0][aRow] = b4.x;
            Bs[aCol4 + 1][aRow] = b4.y;
            Bs[aCol4 + 2][aRow] = b4.z;
            Bs[aCol4 + 3][aRow] = b4.w;
        } else {
            const int bk  = tid >> 5;          // 0..7
            const int bn4 = (tid & 31) * 4;    // 0..124
            float4 b4 = *reinterpret_cast<const float4*>(
                B + (long long)(k0 + bk) * ldb + n0 + bn4);
            *reinterpret_cast<float4*>(&Bs[bk][bn4]) = b4;
        }
        __syncthreads();

#pragma unroll
        for (int kk = 0; kk < 8; kk++) {
            float a[8], b[8];
            *reinterpret_cast<float4*>(a)     = *reinterpret_cast<const float4*>(&As[kk][ty * 8]);
            *reinterpret_cast<float4*>(a + 4) = *reinterpret_cast<const float4*>(&As[kk][ty * 8 + 4]);
            *reinterpret_cast<float4*>(b)     = *reinterpret_cast<const float4*>(&Bs[kk][tx * 8]);
            *reinterpret_cast<float4*>(b + 4) = *reinterpret_cast<const float4*>(&Bs[kk][tx * 8 + 4]);
#pragma unroll
            for (int i = 0; i < 8; i++)
#pragma unroll
                for (int j = 0; j < 8; j++) acc[i][j] += a[i] * b[j];
        }
        __syncthreads();
    }

    // ---- epilogue ----
    float bi[8];
#pragma unroll
    for (int j = 0; j < 8; j++)
        bi[j] = HAS_BIAS ? bias[n0 + tx * 8 + j] : 0.0f;

#pragma unroll
    for (int i = 0; i < 8; i++) {
        const long long row = m0 + ty * 8 + i;
        float4 c0, c1;
        c0.x = alpha * acc[i][0] + bi[0];
        c0.y = alpha * acc[i][1] + bi[1];
        c0.z = alpha * acc[i][2] + bi[2];
        c0.w = alpha * acc[i][3] + bi[3];
        c1.x = alpha * acc[i][4] + bi[4];
        c1.y = alpha * acc[i][5] + bi[5];
        c1.z = alpha * acc[i][6] + bi[6];
        c1.w = alpha * acc[i][7] + bi[7];
        *reinterpret_cast<float4*>(C + row * ldc + n0 + tx * 8)     = c0;
        *reinterpret_cast<float4*>(C + row * ldc + n0 + tx * 8 + 4) = c1;
    }
}

// ----------------------------------------------------------------------------
// Row softmax over S=2048 elements. One block (256 threads) per row,
// 8 elements per thread held in registers.
// ----------------------------------------------------------------------------
__global__ __launch_bounds__(256) void softmax_kernel(float* __restrict__ attn)
{
    const long long row = blockIdx.x;
    float* p = attn + row * (long long)SS;
    const int tid = threadIdx.x;

    float v[8];
#pragma unroll
    for (int i = 0; i < 8; i++) v[i] = p[tid + i * 256];

    float m = -1e30f;
#pragma unroll
    for (int i = 0; i < 8; i++) m = fmaxf(m, v[i]);
#pragma unroll
    for (int o = 16; o > 0; o >>= 1) m = fmaxf(m, __shfl_xor_sync(0xffffffffu, m, o));

    __shared__ float red[8];
    if ((tid & 31) == 0) red[tid >> 5] = m;
    __syncthreads();
    float bm = red[0];
#pragma unroll
    for (int w = 1; w < 8; w++) bm = fmaxf(bm, red[w]);
    __syncthreads();

    float e[8];
    float s = 0.0f;
#pragma unroll
    for (int i = 0; i < 8; i++) { e[i] = __expf(v[i] - bm); s += e[i]; }
#pragma unroll
    for (int o = 16; o > 0; o >>= 1) s += __shfl_xor_sync(0xffffffffu, s, o);
    if ((tid & 31) == 0) red[tid >> 5] = s;
    __syncthreads();
    float bs = 0.0f;
#pragma unroll
    for (int w = 0; w < 8; w++) bs += red[w];
    const float inv = 1.0f / bs;

#pragma unroll
    for (int i = 0; i < 8; i++) p[tid + i * 256] = e[i] * inv;
}

extern "C" void kernel_launch(void* const* d_in, const int* in_sizes, int n_in,
                              void* d_out, int out_size)
{
    const float* Q  = (const float*)d_in[0];
    const float* K  = (const float*)d_in[1];
    const float* V  = (const float*)d_in[2];
    const float* Wq = (const float*)d_in[3];
    const float* bq = (const float*)d_in[4];
    const float* Wk = (const float*)d_in[5];
    const float* bk = (const float*)d_in[6];
    const float* Wv = (const float*)d_in[7];
    const float* bv = (const float*)d_in[8];
    const float* Wo = (const float*)d_in[9];
    const float* bo = (const float*)d_in[10];

    float* out = (float*)d_out;

    const long long OUT_ELEMS  = (long long)BB * SS * DMODEL;           // 4,194,304
    const long long ATTN_ELEMS = (long long)BB * NHEADS * SS * SS;      // 67,108,864

    float *qp, *kp, *vp, *ctxp, *attn_fb;
    cudaGetSymbolAddress((void**)&qp,      g_q);
    cudaGetSymbolAddress((void**)&kp,      g_k);
    cudaGetSymbolAddress((void**)&vp,      g_v);
    cudaGetSymbolAddress((void**)&ctxp,    g_ctx);
    cudaGetSymbolAddress((void**)&attn_fb, g_attn_fallback);

    // Tuple output layout: [out (B*S*D) | attn (B*H*S*S)]
    float* attn = ((long long)out_size >= OUT_ELEMS + ATTN_ELEMS)
                      ? (out + OUT_ELEMS) : attn_fb;

    const int M = BB * SS;   // 4096
    const float inv_sqrt_dk = 0.08838834764831845f;  // 1/sqrt(128)

    dim3 blk(256);

    // 1-3) projections: X @ W^T + b  -> g_{q,k,v}   [4096 x 1024]
    dim3 gProj(DMODEL / 128, M / 128, 1);
    gemm_kernel<true, true><<<gProj, blk>>>(Q, Wq, bq, qp,
        M, DMODEL, DMODEL, DMODEL, DMODEL, DMODEL, 1.0f,
        1, 0, 0, 0, 0, 0, 0);
    gemm_kernel<true, true><<<gProj, blk>>>(K, Wk, bk, kp,
        M, DMODEL, DMODEL, DMODEL, DMODEL, DMODEL, 1.0f,
        1, 0, 0, 0, 0, 0, 0);
    gemm_kernel<true, true><<<gProj, blk>>>(V, Wv, bv, vp,
        M, DMODEL, DMODEL, DMODEL, DMODEL, DMODEL, 1.0f,
        1, 0, 0, 0, 0, 0, 0);

    // 4) scores = q @ k^T / sqrt(dk)   per (b,h): [2048 x 2048], K=128
    dim3 gScores(SS / 128, SS / 128, BB * NHEADS);
    gemm_kernel<true, false><<<gScores, blk>>>(qp, kp, nullptr, attn,
        SS, SS, DK, DMODEL, DMODEL, SS, inv_sqrt_dk,
        NHEADS,
        (long long)SS * DMODEL, (long long)DK,          // A offsets (b,h)
        (long long)SS * DMODEL, (long long)DK,          // B offsets
        (long long)NHEADS * SS * SS, (long long)SS * SS // C offsets
    );

    // 5) softmax over rows of attn
    softmax_kernel<<<BB * NHEADS * SS, blk>>>(attn);

    // 6) ctx = attn @ v   per (b,h): [2048 x 128], K=2048 (B non-transposed)
    dim3 gCtx(DK / 128, SS / 128, BB * NHEADS);
    gemm_kernel<false, false><<<gCtx, blk>>>(attn, vp, nullptr, ctxp,
        SS, DK, SS, SS, DMODEL, DMODEL, 1.0f,
        NHEADS,
        (long long)NHEADS * SS * SS, (long long)SS * SS,
        (long long)SS * DMODEL, (long long)DK,
        (long long)SS * DMODEL, (long long)DK
    );

    // 7) out = ctx @ Wo^T + bo   [4096 x 1024]
    gemm_kernel<true, true><<<gProj, blk>>>(ctxp, Wo, bo, out,
        M, DMODEL, DMODEL, DMODEL, DMODEL, DMODEL, 1.0f,
        1, 0, 0, 0, 0, 0, 0);
}

// round 2
// speedup vs baseline: 1.9422x; 1.9422x over previous
#include <cuda_runtime.h>
#include <math.h>
#include <stdint.h>

#define DMODEL 1024
#define NHEADS 8
#define DK 128
#define BB 2
#define SS 2048

// Scratch (allocation-free rule: __device__ globals)
__device__ float g_q[(size_t)BB * SS * DMODEL];
__device__ float g_k[(size_t)BB * SS * DMODEL];
__device__ float g_v[(size_t)BB * SS * DMODEL];
__device__ float g_ctx[(size_t)BB * SS * DMODEL];
__device__ float g_attn_fallback[(size_t)BB * NHEADS * SS * SS];

__device__ __forceinline__ uint32_t f2tf32(float f) {
    uint32_t u;
    asm("cvt.rna.tf32.f32 %0, %1;" : "=r"(u) : "f"(f));
    return u;
}

__device__ __forceinline__ void mma_tf32(float* c, const uint32_t* a, const uint32_t* b) {
    asm volatile(
        "mma.sync.aligned.m16n8k8.row.col.f32.tf32.tf32.f32 "
        "{%0,%1,%2,%3},{%4,%5,%6,%7},{%8,%9},{%0,%1,%2,%3};"
        : "+f"(c[0]), "+f"(c[1]), "+f"(c[2]), "+f"(c[3])
        : "r"(a[0]), "r"(a[1]), "r"(a[2]), "r"(a[3]), "r"(b[0]), "r"(b[1]));
}

// ----------------------------------------------------------------------------
// Batched TF32 tensor-core GEMM:  C = alpha * A @ op(B) + bias
//   A: [M,K] row-major.  TRANS_B: B is [N,K] (computes A @ B^T); else [K,N].
//   CTA tile 128x128x32, 8 warps (2x4), warp tile 64x32, mma.m16n8k8.tf32.
//   Dims: M%128==0, N%128==0, K%32==0.
// ----------------------------------------------------------------------------
template <bool TRANS_B, bool HAS_BIAS>
__global__ __launch_bounds__(256) void gemm_tf32_kernel(
    const float* __restrict__ A, const float* __restrict__ B,
    const float* __restrict__ bias, float* __restrict__ C,
    int M, int N, int K, int lda, int ldb, int ldc, float alpha,
    int Hdiv,
    long long sAb, long long sAh,
    long long sBb, long long sBh,
    long long sCb, long long sCh)
{
    const int z  = blockIdx.z;
    const int zb = z / Hdiv;
    const int zh = z % Hdiv;
    A += zb * sAb + zh * sAh;
    B += zb * sBb + zh * sBh;
    C += zb * sCb + zh * sCh;

    // [k][m] and [k][n], stride 132 => fragment loads conflict-free
    __shared__ uint32_t As[32][132];
    __shared__ uint32_t Bs[32][132];

    const int tid = threadIdx.x;
    const int m0 = blockIdx.y * 128;
    const int n0 = blockIdx.x * 128;

    const int wid    = tid >> 5;
    const int lane   = tid & 31;
    const int warp_m = wid >> 2;        // 0..1  -> 64 rows each
    const int warp_n = wid & 3;         // 0..3  -> 32 cols each
    const int grp    = lane >> 2;       // 0..7
    const int tig    = lane & 3;        // 0..3

    // loader mapping (both A-style tiles): rows of 32-wide k, float4 chunks
    const int lr  = tid >> 3;           // 0..31
    const int lc4 = (tid & 7) * 4;      // 0,4,...,28

    float acc[4][4][4];
#pragma unroll
    for (int i = 0; i < 4; i++)
#pragma unroll
        for (int j = 0; j < 4; j++)
#pragma unroll
            for (int q = 0; q < 4; q++) acc[i][j][q] = 0.0f;

    for (int k0 = 0; k0 < K; k0 += 32) {
        // ---- load A tile [128m x 32k] -> As[k][m] ----
#pragma unroll
        for (int i = 0; i < 4; i++) {
            const int row = i * 32 + lr;
            float4 a4 = *reinterpret_cast<const float4*>(
                A + (long long)(m0 + row) * lda + k0 + lc4);
            As[lc4 + 0][row] = f2tf32(a4.x);
            As[lc4 + 1][row] = f2tf32(a4.y);
            As[lc4 + 2][row] = f2tf32(a4.z);
            As[lc4 + 3][row] = f2tf32(a4.w);
        }
        // ---- load B tile -> Bs[k][n] ----
        if (TRANS_B) {
#pragma unroll
            for (int i = 0; i < 4; i++) {
                const int row = i * 32 + lr;   // n index
                float4 b4 = *reinterpret_cast<const float4*>(
                    B + (long long)(n0 + row) * ldb + k0 + lc4);
                Bs[lc4 + 0][row] = f2tf32(b4.x);
                Bs[lc4 + 1][row] = f2tf32(b4.y);
                Bs[lc4 + 2][row] = f2tf32(b4.z);
                Bs[lc4 + 3][row] = f2tf32(b4.w);
            }
        } else {
            const int bk = tid >> 3;            // 0..31 (k index)
#pragma unroll
            for (int i = 0; i < 4; i++) {
                const int n4 = (tid & 7) * 4 + i * 32;
                float4 b4 = *reinterpret_cast<const float4*>(
                    B + (long long)(k0 + bk) * ldb + n0 + n4);
                uint4 u;
                u.x = f2tf32(b4.x); u.y = f2tf32(b4.y);
                u.z = f2tf32(b4.z); u.w = f2tf32(b4.w);
                *reinterpret_cast<uint4*>(&Bs[bk][n4]) = u;
            }
        }
        __syncthreads();

#pragma unroll
        for (int ks = 0; ks < 4; ks++) {
            const int kb = ks * 8;
            uint32_t af[4][4], bf[4][2];
#pragma unroll
            for (int mi = 0; mi < 4; mi++) {
                const int rb = warp_m * 64 + mi * 16;
                af[mi][0] = As[kb + tig    ][rb + grp    ];
                af[mi][1] = As[kb + tig    ][rb + grp + 8];
                af[mi][2] = As[kb + tig + 4][rb + grp    ];
                af[mi][3] = As[kb + tig + 4][rb + grp + 8];
            }
#pragma unroll
            for (int nj = 0; nj < 4; nj++) {
                const int nb = warp_n * 32 + nj * 8 + grp;
                bf[nj][0] = Bs[kb + tig    ][nb];
                bf[nj][1] = Bs[kb + tig + 4][nb];
            }
#pragma unroll
            for (int mi = 0; mi < 4; mi++)
#pragma unroll
                for (int nj = 0; nj < 4; nj++)
                    mma_tf32(acc[mi][nj], af[mi], bf[nj]);
        }
        __syncthreads();
    }

    // ---- epilogue ----
#pragma unroll
    for (int nj = 0; nj < 4; nj++) {
        const int cc = n0 + warp_n * 32 + nj * 8 + tig * 2;
        float b0 = 0.0f, b1 = 0.0f;
        if (HAS_BIAS) { b0 = bias[cc]; b1 = bias[cc + 1]; }
#pragma unroll
        for (int mi = 0; mi < 4; mi++) {
            const long long r0 = m0 + warp_m * 64 + mi * 16 + grp;
            const long long r1 = r0 + 8;
            float2 v0, v1;
            v0.x = alpha * acc[mi][nj][0] + b0;
            v0.y = alpha * acc[mi][nj][1] + b1;
            v1.x = alpha * acc[mi][nj][2] + b0;
            v1.y = alpha * acc[mi][nj][3] + b1;
            *reinterpret_cast<float2*>(C + r0 * ldc + cc) = v0;
            *reinterpret_cast<float2*>(C + r1 * ldc + cc) = v1;
        }
    }
}

// ----------------------------------------------------------------------------
// Row softmax over S=2048. One block (256 threads) per row.
// ----------------------------------------------------------------------------
__global__ __launch_bounds__(256) void softmax_kernel(float* __restrict__ attn)
{
    const long long row = blockIdx.x;
    float* p = attn + row * (long long)SS;
    const int tid = threadIdx.x;

    float v[8];
#pragma unroll
    for (int i = 0; i < 8; i++) v[i] = p[tid + i * 256];

    float m = -1e30f;
#pragma unroll
    for (int i = 0; i < 8; i++) m = fmaxf(m, v[i]);
#pragma unroll
    for (int o = 16; o > 0; o >>= 1) m = fmaxf(m, __shfl_xor_sync(0xffffffffu, m, o));

    __shared__ float red[8];
    if ((tid & 31) == 0) red[tid >> 5] = m;
    __syncthreads();
    float bm = red[0];
#pragma unroll
    for (int w = 1; w < 8; w++) bm = fmaxf(bm, red[w]);
    __syncthreads();

    float e[8];
    float s = 0.0f;
#pragma unroll
    for (int i = 0; i < 8; i++) { e[i] = __expf(v[i] - bm); s += e[i]; }
#pragma unroll
    for (int o = 16; o > 0; o >>= 1) s += __shfl_xor_sync(0xffffffffu, s, o);
    if ((tid & 31) == 0) red[tid >> 5] = s;
    __syncthreads();
    float bs = 0.0f;
#pragma unroll
    for (int w = 0; w < 8; w++) bs += red[w];
    const float inv = 1.0f / bs;

#pragma unroll
    for (int i = 0; i < 8; i++) p[tid + i * 256] = e[i] * inv;
}

extern "C" void kernel_launch(void* const* d_in, const int* in_sizes, int n_in,
                              void* d_out, int out_size)
{
    const float* Q  = (const float*)d_in[0];
    const float* K  = (const float*)d_in[1];
    const float* V  = (const float*)d_in[2];
    const float* Wq = (const float*)d_in[3];
    const float* bq = (const float*)d_in[4];
    const float* Wk = (const float*)d_in[5];
    const float* bk = (const float*)d_in[6];
    const float* Wv = (const float*)d_in[7];
    const float* bv = (const float*)d_in[8];
    const float* Wo = (const float*)d_in[9];
    const float* bo = (const float*)d_in[10];

    float* out = (float*)d_out;

    const long long OUT_ELEMS  = (long long)BB * SS * DMODEL;           // 4,194,304
    const long long ATTN_ELEMS = (long long)BB * NHEADS * SS * SS;      // 67,108,864

    float *qp, *kp, *vp, *ctxp, *attn_fb;
    cudaGetSymbolAddress((void**)&qp,      g_q);
    cudaGetSymbolAddress((void**)&kp,      g_k);
    cudaGetSymbolAddress((void**)&vp,      g_v);
    cudaGetSymbolAddress((void**)&ctxp,    g_ctx);
    cudaGetSymbolAddress((void**)&attn_fb, g_attn_fallback);

    // Tuple output layout: [out (B*S*D) | attn (B*H*S*S)]
    float* attn = ((long long)out_size >= OUT_ELEMS + ATTN_ELEMS)
                      ? (out + OUT_ELEMS) : attn_fb;

    const int M = BB * SS;   // 4096
    const float inv_sqrt_dk = 0.08838834764831845f;  // 1/sqrt(128)

    dim3 blk(256);

    // 1-3) projections: X @ W^T + b  -> g_{q,k,v}   [4096 x 1024]
    dim3 gProj(DMODEL / 128, M / 128, 1);
    gemm_tf32_kernel<true, true><<<gProj, blk>>>(Q, Wq, bq, qp,
        M, DMODEL, DMODEL, DMODEL, DMODEL, DMODEL, 1.0f,
        1, 0, 0, 0, 0, 0, 0);
    gemm_tf32_kernel<true, true><<<gProj, blk>>>(K, Wk, bk, kp,
        M, DMODEL, DMODEL, DMODEL, DMODEL, DMODEL, 1.0f,
        1, 0, 0, 0, 0, 0, 0);
    gemm_tf32_kernel<true, true><<<gProj, blk>>>(V, Wv, bv, vp,
        M, DMODEL, DMODEL, DMODEL, DMODEL, DMODEL, 1.0f,
        1, 0, 0, 0, 0, 0, 0);

    // 4) scores = q @ k^T / sqrt(dk)   per (b,h): [2048 x 2048], K=128
    dim3 gScores(SS / 128, SS / 128, BB * NHEADS);
    gemm_tf32_kernel<true, false><<<gScores, blk>>>(qp, kp, nullptr, attn,
        SS, SS, DK, DMODEL, DMODEL, SS, inv_sqrt_dk,
        NHEADS,
        (long long)SS * DMODEL, (long long)DK,
        (long long)SS * DMODEL, (long long)DK,
        (long long)NHEADS * SS * SS, (long long)SS * SS);

    // 5) softmax over rows of attn
    softmax_kernel<<<BB * NHEADS * SS, blk>>>(attn);

    // 6) ctx = attn @ v   per (b,h): [2048 x 128], K=2048 (B non-transposed)
    dim3 gCtx(DK / 128, SS / 128, BB * NHEADS);
    gemm_tf32_kernel<false, false><<<gCtx, blk>>>(attn, vp, nullptr, ctxp,
        SS, DK, SS, SS, DMODEL, DMODEL, 1.0f,
        NHEADS,
        (long long)NHEADS * SS * SS, (long long)SS * SS,
        (long long)SS * DMODEL, (long long)DK,
        (long long)SS * DMODEL, (long long)DK);

    // 7) out = ctx @ Wo^T + bo   [4096 x 1024]
    gemm_tf32_kernel<true, true><<<gProj, blk>>>(ctxp, Wo, bo, out,
        M, DMODEL, DMODEL, DMODEL, DMODEL, DMODEL, 1.0f,
        1, 0, 0, 0, 0, 0, 0);
}

// round 3
// speedup vs baseline: 2.6593x; 1.3692x over previous
#include <cuda_runtime.h>
#include <math.h>
#include <stdint.h>

#define DMODEL 1024
#define NHEADS 8
#define DK 128
#define BB 2
#define SS 2048

// Scratch (allocation-free rule: __device__ globals)
__device__ float g_q[(size_t)BB * SS * DMODEL];
__device__ float g_k[(size_t)BB * SS * DMODEL];
__device__ float g_v[(size_t)BB * SS * DMODEL];
__device__ float g_ctx[(size_t)BB * SS * DMODEL];
__device__ float g_attn_fallback[(size_t)BB * NHEADS * SS * SS];

__device__ __forceinline__ uint32_t f2tf32(float f) {
    uint32_t u;
    asm("cvt.rna.tf32.f32 %0, %1;" : "=r"(u) : "f"(f));
    return u;
}

__device__ __forceinline__ void mma_tf32(float* c, const uint32_t* a, const uint32_t* b) {
    asm volatile(
        "mma.sync.aligned.m16n8k8.row.col.f32.tf32.tf32.f32 "
        "{%0,%1,%2,%3},{%4,%5,%6,%7},{%8,%9},{%0,%1,%2,%3};"
        : "+f"(c[0]), "+f"(c[1]), "+f"(c[2]), "+f"(c[3])
        : "r"(a[0]), "r"(a[1]), "r"(a[2]), "r"(a[3]), "r"(b[0]), "r"(b[1]));
}

// smem geometry (uint32 words)
#define AS_STRIDE 36            // [m][k] pad: frag LDS bank = grp*4+tig (unique)
#define BS_KN_STRIDE 136        // [k][n] pad: frag LDS bank = tig*8+grp (unique)
#define AS_WORDS (128 * AS_STRIDE)          // 4608
#define BUF_WORDS (AS_WORDS + AS_WORDS)     // 9216 (B region sized for max layout)
#define GEMM_SMEM_BYTES (2 * BUF_WORDS * 4) // 73728

// ----------------------------------------------------------------------------
// Batched TF32 tensor-core GEMM, double-buffered + register prefetch.
//   C = alpha * A @ op(B) + bias
//   A: [M,K] row-major.  TRANS_B: B is [N,K] (A @ B^T); else [K,N].
//   CTA tile 128x128x32, 8 warps (2x4), warp tile 64x32, mma.m16n8k8.tf32.
//   M%128==0, N%128==0, K%32==0.
// ----------------------------------------------------------------------------
template <bool TRANS_B, bool HAS_BIAS>
__global__ __launch_bounds__(256) void gemm_tf32_kernel(
    const float* __restrict__ A, const float* __restrict__ B,
    const float* __restrict__ bias, float* __restrict__ C,
    int M, int N, int K, int lda, int ldb, int ldc, float alpha,
    int Hdiv,
    long long sAb, long long sAh,
    long long sBb, long long sBh,
    long long sCb, long long sCh)
{
    extern __shared__ uint32_t smem[];

    const int z  = blockIdx.z;
    const int zb = z / Hdiv;
    const int zh = z % Hdiv;
    A += zb * sAb + zh * sAh;
    B += zb * sBb + zh * sBh;
    C += zb * sCb + zh * sCh;

    const int tid  = threadIdx.x;
    const int m0   = blockIdx.y * 128;
    const int n0   = blockIdx.x * 128;
    const int wid  = tid >> 5;
    const int lane = tid & 31;
    const int warp_m = wid >> 2;    // 0..1
    const int warp_n = wid & 3;     // 0..3
    const int grp  = lane >> 2;     // 0..7
    const int tig  = lane & 3;      // 0..3

    // loader mapping: 4 float4 per thread per tile
    const int lr = tid >> 3;        // 0..31
    const int lc = (tid & 7) * 4;   // 0,4,...,28

    float acc[4][4][4];
#pragma unroll
    for (int i = 0; i < 4; i++)
#pragma unroll
        for (int j = 0; j < 4; j++)
#pragma unroll
            for (int q = 0; q < 4; q++) acc[i][j][q] = 0.0f;

    float4 pa[4], pb[4];

    // ---------------- helpers (expanded inline) ----------------
#define LOAD_A(k0)                                                            \
    _Pragma("unroll")                                                         \
    for (int i = 0; i < 4; i++)                                               \
        pa[i] = *reinterpret_cast<const float4*>(                             \
            A + (long long)(m0 + lr + i * 32) * lda + (k0) + lc);

#define LOAD_B(k0)                                                            \
    if (TRANS_B) {                                                            \
        _Pragma("unroll")                                                     \
        for (int i = 0; i < 4; i++)                                           \
            pb[i] = *reinterpret_cast<const float4*>(                         \
                B + (long long)(n0 + lr + i * 32) * ldb + (k0) + lc);         \
    } else {                                                                  \
        _Pragma("unroll")                                                     \
        for (int i = 0; i < 4; i++)                                           \
            pb[i] = *reinterpret_cast<const float4*>(                         \
                B + (long long)((k0) + lr) * ldb + n0 + lc + i * 32);         \
    }

#define STS_TILE(bufidx)                                                      \
    {                                                                         \
        uint32_t* Asb = smem + (bufidx) * BUF_WORDS;                          \
        uint32_t* Bsb = Asb + AS_WORDS;                                       \
        _Pragma("unroll")                                                     \
        for (int i = 0; i < 4; i++) {                                         \
            uint4 u;                                                          \
            u.x = f2tf32(pa[i].x); u.y = f2tf32(pa[i].y);                     \
            u.z = f2tf32(pa[i].z); u.w = f2tf32(pa[i].w);                     \
            *reinterpret_cast<uint4*>(&Asb[(lr + i * 32) * AS_STRIDE + lc]) = u; \
        }                                                                     \
        if (TRANS_B) {                                                        \
            _Pragma("unroll")                                                 \
            for (int i = 0; i < 4; i++) {                                     \
                uint4 u;                                                      \
                u.x = f2tf32(pb[i].x); u.y = f2tf32(pb[i].y);                 \
                u.z = f2tf32(pb[i].z); u.w = f2tf32(pb[i].w);                 \
                *reinterpret_cast<uint4*>(&Bsb[(lr + i * 32) * AS_STRIDE + lc]) = u; \
            }                                                                 \
        } else {                                                              \
            _Pragma("unroll")                                                 \
            for (int i = 0; i < 4; i++) {                                     \
                uint4 u;                                                      \
                u.x = f2tf32(pb[i].x); u.y = f2tf32(pb[i].y);                 \
                u.z = f2tf32(pb[i].z); u.w = f2tf32(pb[i].w);                 \
                *reinterpret_cast<uint4*>(&Bsb[lr * BS_KN_STRIDE + lc + i * 32]) = u; \
            }                                                                 \
        }                                                                     \
    }

#define COMPUTE(bufidx)                                                       \
    {                                                                         \
        const uint32_t* Asb = smem + (bufidx) * BUF_WORDS;                    \
        const uint32_t* Bsb = Asb + AS_WORDS;                                 \
        _Pragma("unroll")                                                     \
        for (int ks = 0; ks < 4; ks++) {                                      \
            const int kb = ks * 8;                                            \
            uint32_t af[4][4], bf[4][2];                                      \
            _Pragma("unroll")                                                 \
            for (int mi = 0; mi < 4; mi++) {                                  \
                const int rb = warp_m * 64 + mi * 16;                         \
                af[mi][0] = Asb[(rb + grp    ) * AS_STRIDE + kb + tig    ];   \
                af[mi][1] = Asb[(rb + grp + 8) * AS_STRIDE + kb + tig    ];   \
                af[mi][2] = Asb[(rb + grp    ) * AS_STRIDE + kb + tig + 4];   \
                af[mi][3] = Asb[(rb + grp + 8) * AS_STRIDE + kb + tig + 4];   \
            }                                                                 \
            _Pragma("unroll")                                                 \
            for (int nj = 0; nj < 4; nj++) {                                  \
                const int nb = warp_n * 32 + nj * 8 + grp;                    \
                if (TRANS_B) {                                                \
                    bf[nj][0] = Bsb[nb * AS_STRIDE + kb + tig    ];           \
                    bf[nj][1] = Bsb[nb * AS_STRIDE + kb + tig + 4];           \
                } else {                                                      \
                    bf[nj][0] = Bsb[(kb + tig    ) * BS_KN_STRIDE + nb];      \
                    bf[nj][1] = Bsb[(kb + tig + 4) * BS_KN_STRIDE + nb];      \
                }                                                             \
            }                                                                 \
            _Pragma("unroll")                                                 \
            for (int mi = 0; mi < 4; mi++)                                    \
                _Pragma("unroll")                                             \
                for (int nj = 0; nj < 4; nj++)                                \
                    mma_tf32(acc[mi][nj], af[mi], bf[nj]);                    \
        }                                                                     \
    }
    // ------------------------------------------------------------

    // prologue: fill buffer 0
    LOAD_A(0)
    LOAD_B(0)
    STS_TILE(0)
    __syncthreads();

    int buf = 0;
    for (int k0 = 0; k0 < K; k0 += 32) {
        const bool more = (k0 + 32) < K;
        if (more) {
            LOAD_A(k0 + 32)
            LOAD_B(k0 + 32)
        }
        COMPUTE(buf)
        if (more) STS_TILE(buf ^ 1)
        __syncthreads();
        buf ^= 1;
    }

    // ---- epilogue (identical to R2) ----
#pragma unroll
    for (int nj = 0; nj < 4; nj++) {
        const int cc = n0 + warp_n * 32 + nj * 8 + tig * 2;
        float b0 = 0.0f, b1 = 0.0f;
        if (HAS_BIAS) { b0 = bias[cc]; b1 = bias[cc + 1]; }
#pragma unroll
        for (int mi = 0; mi < 4; mi++) {
            const long long r0 = m0 + warp_m * 64 + mi * 16 + grp;
            const long long r1 = r0 + 8;
            float2 v0, v1;
            v0.x = alpha * acc[mi][nj][0] + b0;
            v0.y = alpha * acc[mi][nj][1] + b1;
            v1.x = alpha * acc[mi][nj][2] + b0;
            v1.y = alpha * acc[mi][nj][3] + b1;
            *reinterpret_cast<float2*>(C + r0 * ldc + cc) = v0;
            *reinterpret_cast<float2*>(C + r1 * ldc + cc) = v1;
        }
    }
#undef LOAD_A
#undef LOAD_B
#undef STS_TILE
#undef COMPUTE
}

// ----------------------------------------------------------------------------
// Row softmax over S=2048. One block (256 threads) per row.
// ----------------------------------------------------------------------------
__global__ __launch_bounds__(256) void softmax_kernel(float* __restrict__ attn)
{
    const long long row = blockIdx.x;
    float* p = attn + row * (long long)SS;
    const int tid = threadIdx.x;

    float v[8];
#pragma unroll
    for (int i = 0; i < 8; i++) v[i] = p[tid + i * 256];

    float m = -1e30f;
#pragma unroll
    for (int i = 0; i < 8; i++) m = fmaxf(m, v[i]);
#pragma unroll
    for (int o = 16; o > 0; o >>= 1) m = fmaxf(m, __shfl_xor_sync(0xffffffffu, m, o));

    __shared__ float red[8];
    if ((tid & 31) == 0) red[tid >> 5] = m;
    __syncthreads();
    float bm = red[0];
#pragma unroll
    for (int w = 1; w < 8; w++) bm = fmaxf(bm, red[w]);
    __syncthreads();

    float e[8];
    float s = 0.0f;
#pragma unroll
    for (int i = 0; i < 8; i++) { e[i] = __expf(v[i] - bm); s += e[i]; }
#pragma unroll
    for (int o = 16; o > 0; o >>= 1) s += __shfl_xor_sync(0xffffffffu, s, o);
    if ((tid & 31) == 0) red[tid >> 5] = s;
    __syncthreads();
    float bs = 0.0f;
#pragma unroll
    for (int w = 0; w < 8; w++) bs += red[w];
    const float inv = 1.0f / bs;

#pragma unroll
    for (int i = 0; i < 8; i++) p[tid + i * 256] = e[i] * inv;
}

extern "C" void kernel_launch(void* const* d_in, const int* in_sizes, int n_in,
                              void* d_out, int out_size)
{
    const float* Q  = (const float*)d_in[0];
    const float* K  = (const float*)d_in[1];
    const float* V  = (const float*)d_in[2];
    const float* Wq = (const float*)d_in[3];
    const float* bq = (const float*)d_in[4];
    const float* Wk = (const float*)d_in[5];
    const float* bk = (const float*)d_in[6];
    const float* Wv = (const float*)d_in[7];
    const float* bv = (const float*)d_in[8];
    const float* Wo = (const float*)d_in[9];
    const float* bo = (const float*)d_in[10];

    float* out = (float*)d_out;

    const long long OUT_ELEMS  = (long long)BB * SS * DMODEL;           // 4,194,304
    const long long ATTN_ELEMS = (long long)BB * NHEADS * SS * SS;      // 67,108,864

    float *qp, *kp, *vp, *ctxp, *attn_fb;
    cudaGetSymbolAddress((void**)&qp,      g_q);
    cudaGetSymbolAddress((void**)&kp,      g_k);
    cudaGetSymbolAddress((void**)&vp,      g_v);
    cudaGetSymbolAddress((void**)&ctxp,    g_ctx);
    cudaGetSymbolAddress((void**)&attn_fb, g_attn_fallback);

    // Tuple output layout: [out (B*S*D) | attn (B*H*S*S)]
    float* attn = ((long long)out_size >= OUT_ELEMS + ATTN_ELEMS)
                      ? (out + OUT_ELEMS) : attn_fb;

    // raise dynamic smem limits (idempotent, host-side, capture-safe)
    cudaFuncSetAttribute(gemm_tf32_kernel<true, true>,
                         cudaFuncAttributeMaxDynamicSharedMemorySize, GEMM_SMEM_BYTES);
    cudaFuncSetAttribute(gemm_tf32_kernel<true, false>,
                         cudaFuncAttributeMaxDynamicSharedMemorySize, GEMM_SMEM_BYTES);
    cudaFuncSetAttribute(gemm_tf32_kernel<false, false>,
                         cudaFuncAttributeMaxDynamicSharedMemorySize, GEMM_SMEM_BYTES);

    const int M = BB * SS;   // 4096
    const float inv_sqrt_dk = 0.08838834764831845f;  // 1/sqrt(128)

    dim3 blk(256);

    // 1-3) projections: X @ W^T + b  -> g_{q,k,v}   [4096 x 1024]
    dim3 gProj(DMODEL / 128, M / 128, 1);
    gemm_tf32_kernel<true, true><<<gProj, blk, GEMM_SMEM_BYTES>>>(Q, Wq, bq, qp,
        M, DMODEL, DMODEL, DMODEL, DMODEL, DMODEL, 1.0f,
        1, 0, 0, 0, 0, 0, 0);
    gemm_tf32_kernel<true, true><<<gProj, blk, GEMM_SMEM_BYTES>>>(K, Wk, bk, kp,
        M, DMODEL, DMODEL, DMODEL, DMODEL, DMODEL, 1.0f,
        1, 0, 0, 0, 0, 0, 0);
    gemm_tf32_kernel<true, true><<<gProj, blk, GEMM_SMEM_BYTES>>>(V, Wv, bv, vp,
        M, DMODEL, DMODEL, DMODEL, DMODEL, DMODEL, 1.0f,
        1, 0, 0, 0, 0, 0, 0);

    // 4) scores = q @ k^T / sqrt(dk)   per (b,h): [2048 x 2048], K=128
    dim3 gScores(SS / 128, SS / 128, BB * NHEADS);
    gemm_tf32_kernel<true, false><<<gScores, blk, GEMM_SMEM_BYTES>>>(qp, kp, nullptr, attn,
        SS, SS, DK, DMODEL, DMODEL, SS, inv_sqrt_dk,
        NHEADS,
        (long long)SS * DMODEL, (long long)DK,
        (long long)SS * DMODEL, (long long)DK,
        (long long)NHEADS * SS * SS, (long long)SS * SS);

    // 5) softmax over rows of attn
    softmax_kernel<<<BB * NHEADS * SS, blk>>>(attn);

    // 6) ctx = attn @ v   per (b,h): [2048 x 128], K=2048 (B non-transposed)
    dim3 gCtx(DK / 128, SS / 128, BB * NHEADS);
    gemm_tf32_kernel<false, false><<<gCtx, blk, GEMM_SMEM_BYTES>>>(attn, vp, nullptr, ctxp,
        SS, DK, SS, SS, DMODEL, DMODEL, 1.0f,
        NHEADS,
        (long long)NHEADS * SS * SS, (long long)SS * SS,
        (long long)SS * DMODEL, (long long)DK,
        (long long)SS * DMODEL, (long long)DK);

    // 7) out = ctx @ Wo^T + bo   [4096 x 1024]
    gemm_tf32_kernel<true, true><<<gProj, blk, GEMM_SMEM_BYTES>>>(ctxp, Wo, bo, out,
        M, DMODEL, DMODEL, DMODEL, DMODEL, DMODEL, 1.0f,
        1, 0, 0, 0, 0, 0, 0);
}

// round 6
// speedup vs baseline: 3.0911x; 1.1624x over previous
#include <cuda_runtime.h>
#include <math.h>
#include <stdint.h>

#define DMODEL 1024
#define NHEADS 8
#define DK 128
#define BB 2
#define SS 2048

// Scratch (allocation-free rule: __device__ globals)
__device__ float g_q[(size_t)BB * SS * DMODEL];
__device__ float g_k[(size_t)BB * SS * DMODEL];
__device__ float g_v[(size_t)BB * SS * DMODEL];
__device__ float g_vt[(size_t)BB * NHEADS * DK * SS];
__device__ float g_ctx[(size_t)BB * SS * DMODEL];
__device__ float g_attn_fallback[(size_t)BB * NHEADS * SS * SS];

__device__ __forceinline__ uint32_t smem_u32(const void* p) {
    uint32_t a;
    asm("{ .reg .u64 t; cvta.to.shared.u64 t, %1; cvt.u32.u64 %0, t; }" : "=r"(a) : "l"(p));
    return a;
}
__device__ __forceinline__ uint32_t f2tf32(float f) {
    uint32_t u;
    asm("cvt.rna.tf32.f32 %0, %1;" : "=r"(u) : "f"(f));
    return u;
}
__device__ __forceinline__ void mma_tf32(float* c, const uint32_t* a, const uint32_t* b) {
    asm volatile(
        "mma.sync.aligned.m16n8k8.row.col.f32.tf32.tf32.f32 "
        "{%0,%1,%2,%3},{%4,%5,%6,%7},{%8,%9},{%0,%1,%2,%3};"
        : "+f"(c[0]), "+f"(c[1]), "+f"(c[2]), "+f"(c[3])
        : "r"(a[0]), "r"(a[1]), "r"(a[2]), "r"(a[3]), "r"(b[0]), "r"(b[1]));
}
__device__ __forceinline__ void cp_async16(uint32_t saddr, const void* gaddr) {
    asm volatile("cp.async.cg.shared.global [%0], [%1], 16;"
                 :: "r"(saddr), "l"(gaddr) : "memory");
}
#define CP_COMMIT() asm volatile("cp.async.commit_group;" ::: "memory")
#define CP_WAIT2()  asm volatile("cp.async.wait_group 2;" ::: "memory")

// smem word index for (row m, k-word k) within a 128x16-word operand tile.
// XOR swizzle: conflict-free for 16B cp.async stores AND all mma fragment LDS.
#define SW_WORD(m, k) ((uint32_t)(m) * 16u + ((uint32_t)(k) ^ (((((uint32_t)(m)) >> 1) & 3u) << 2)))

#define STAGE_BYTES 16384u           // A(8KB) + B(8KB)
#define NSTAGE 4
#define GEMM_SMEM_BYTES (NSTAGE * STAGE_BYTES)   // 65536

// ----------------------------------------------------------------------------
// Batched TF32 tensor-core GEMM, cp.async 4-stage pipeline.
//   C = alpha * A @ B^T + bias
//   A: [M,K] row-major (lda).  B: [N,K] row-major (ldb).
//   CTA tile 128x128, K-stage 16, 8 warps (2x4), warp tile 64x32, m16n8k8.tf32.
//   M%128==0, N%128==0, K%16==0, K>=64.
//   NOTE: one commit_group is issued EVERY loop iteration (empty groups in the
//   tail) so that wait_group 2 at iteration s always covers stage s's copies.
// ----------------------------------------------------------------------------
template <bool HAS_BIAS>
__global__ __launch_bounds__(256, 2) void gemm_cp_kernel(
    const float* __restrict__ A, const float* __restrict__ B,
    const float* __restrict__ bias, float* __restrict__ C,
    int K, int lda, int ldb, int ldc, float alpha,
    int Hdiv,
    long long sAb, long long sAh,
    long long sBb, long long sBh,
    long long sCb, long long sCh)
{
    extern __shared__ char smem[];
    const uint32_t sb = smem_u32(smem);

    const int z  = blockIdx.z;
    const int zb = z / Hdiv;
    const int zh = z % Hdiv;
    A += zb * sAb + zh * sAh;
    B += zb * sBb + zh * sBh;
    C += zb * sCb + zh * sCh;

    const int tid  = threadIdx.x;
    const int wid  = tid >> 5;
    const int lane = tid & 31;
    const int m0   = blockIdx.y * 128;
    const int n0   = blockIdx.x * 128;
    const int warp_m = wid >> 2;    // 0..1
    const int warp_n = wid & 3;     // 0..3
    const int grp  = lane >> 2;     // 0..7
    const int tig  = lane & 3;      // 0..3

    // cp.async loader mapping: thread t covers rows (t>>2)+{0,64}, 16B chunk (t&3)
    const int lm = tid >> 2;        // 0..63
    const int lc = (tid & 3) * 4;   // k word 0,4,8,12

    float acc[4][4][4];
#pragma unroll
    for (int i = 0; i < 4; i++)
#pragma unroll
        for (int j = 0; j < 4; j++)
#pragma unroll
            for (int q = 0; q < 4; q++) acc[i][j][q] = 0.0f;

    // issues copies only; caller commits
#define ISSUE_BODY(bufi, k0)                                                    \
    {                                                                           \
        const uint32_t ab = sb + (uint32_t)(bufi) * STAGE_BYTES;                \
        const uint32_t bbs = ab + 8192u;                                        \
        _Pragma("unroll")                                                       \
        for (int i = 0; i < 2; i++) {                                           \
            const int m = lm + i * 64;                                          \
            cp_async16(ab + SW_WORD(m, lc) * 4u,                                \
                       A + (long long)(m0 + m) * lda + (k0) + lc);              \
            cp_async16(bbs + SW_WORD(m, lc) * 4u,                               \
                       B + (long long)(n0 + m) * ldb + (k0) + lc);              \
        }                                                                       \
    }

#define COMPUTE(bufi)                                                           \
    {                                                                           \
        const float* ab = reinterpret_cast<const float*>(                       \
            smem + (uint32_t)(bufi) * STAGE_BYTES);                             \
        const float* bbs = ab + 2048;                                           \
        _Pragma("unroll")                                                       \
        for (int ks = 0; ks < 2; ks++) {                                        \
            const int kb = ks * 8;                                              \
            uint32_t af[4][4], bf[4][2];                                        \
            _Pragma("unroll")                                                   \
            for (int mi = 0; mi < 4; mi++) {                                    \
                const int ra = warp_m * 64 + mi * 16 + grp;                     \
                af[mi][0] = f2tf32(ab[SW_WORD(ra,     kb + tig    )]);          \
                af[mi][1] = f2tf32(ab[SW_WORD(ra + 8, kb + tig    )]);          \
                af[mi][2] = f2tf32(ab[SW_WORD(ra,     kb + tig + 4)]);          \
                af[mi][3] = f2tf32(ab[SW_WORD(ra + 8, kb + tig + 4)]);          \
            }                                                                   \
            _Pragma("unroll")                                                   \
            for (int nj = 0; nj < 4; nj++) {                                    \
                const int nb = warp_n * 32 + nj * 8 + grp;                      \
                bf[nj][0] = f2tf32(bbs[SW_WORD(nb, kb + tig    )]);             \
                bf[nj][1] = f2tf32(bbs[SW_WORD(nb, kb + tig + 4)]);             \
            }                                                                   \
            _Pragma("unroll")                                                   \
            for (int mi = 0; mi < 4; mi++)                                      \
                _Pragma("unroll")                                               \
                for (int nj = 0; nj < 4; nj++)                                  \
                    mma_tf32(acc[mi][nj], af[mi], bf[nj]);                      \
        }                                                                       \
    }

    const int S = K >> 4;   // stages of 16

    // prologue: 3 stages in flight (each its own group)
    ISSUE_BODY(0, 0)   CP_COMMIT();
    ISSUE_BODY(1, 16)  CP_COMMIT();
    ISSUE_BODY(2, 32)  CP_COMMIT();

    for (int s = 0; s < S; s++) {
        CP_WAIT2();
        __syncthreads();
        COMPUTE(s & 3)
        if (s + 3 < S) {
            ISSUE_BODY((s + 3) & 3, (s + 3) * 16)
        }
        CP_COMMIT();   // unconditional: keeps wait_group accounting exact in the tail
    }

    // ---- epilogue (identical to R2/R3) ----
#pragma unroll
    for (int nj = 0; nj < 4; nj++) {
        const int cc = n0 + warp_n * 32 + nj * 8 + tig * 2;
        float b0 = 0.0f, b1 = 0.0f;
        if (HAS_BIAS) { b0 = bias[cc]; b1 = bias[cc + 1]; }
#pragma unroll
        for (int mi = 0; mi < 4; mi++) {
            const long long r0 = m0 + warp_m * 64 + mi * 16 + grp;
            const long long r1 = r0 + 8;
            float2 v0, v1;
            v0.x = alpha * acc[mi][nj][0] + b0;
            v0.y = alpha * acc[mi][nj][1] + b1;
            v1.x = alpha * acc[mi][nj][2] + b0;
            v1.y = alpha * acc[mi][nj][3] + b1;
            *reinterpret_cast<float2*>(C + r0 * ldc + cc) = v0;
            *reinterpret_cast<float2*>(C + r1 * ldc + cc) = v1;
        }
    }
#undef ISSUE_BODY
#undef COMPUTE
}

// ----------------------------------------------------------------------------
// V transpose: g_v [(b*S+s)][h*128+n]  ->  g_vt [((b*8+h)*128+n)][s]
// ----------------------------------------------------------------------------
__global__ void transpose_v_kernel(const float* __restrict__ v, float* __restrict__ vt)
{
    __shared__ float t[32][33];
    const int z = blockIdx.z, b = z >> 3, h = z & 7;
    const int s0 = blockIdx.x * 32, n0 = blockIdx.y * 32;
    const int tx = threadIdx.x, ty = threadIdx.y;
#pragma unroll
    for (int j = ty; j < 32; j += 8)
        t[j][tx] = v[((long long)b * SS + s0 + j) * DMODEL + h * DK + n0 + tx];
    __syncthreads();
#pragma unroll
    for (int j = ty; j < 32; j += 8)
        vt[((long long)z * DK + n0 + j) * SS + s0 + tx] = t[tx][j];
}

// ----------------------------------------------------------------------------
// Row softmax over S=2048. One block (256 threads) per row.
// ----------------------------------------------------------------------------
__global__ __launch_bounds__(256) void softmax_kernel(float* __restrict__ attn)
{
    const long long row = blockIdx.x;
    float* p = attn + row * (long long)SS;
    const int tid = threadIdx.x;

    float v[8];
#pragma unroll
    for (int i = 0; i < 8; i++) v[i] = p[tid + i * 256];

    float m = -1e30f;
#pragma unroll
    for (int i = 0; i < 8; i++) m = fmaxf(m, v[i]);
#pragma unroll
    for (int o = 16; o > 0; o >>= 1) m = fmaxf(m, __shfl_xor_sync(0xffffffffu, m, o));

    __shared__ float red[8];
    if ((tid & 31) == 0) red[tid >> 5] = m;
    __syncthreads();
    float bm = red[0];
#pragma unroll
    for (int w = 1; w < 8; w++) bm = fmaxf(bm, red[w]);
    __syncthreads();

    float e[8];
    float s = 0.0f;
#pragma unroll
    for (int i = 0; i < 8; i++) { e[i] = __expf(v[i] - bm); s += e[i]; }
#pragma unroll
    for (int o = 16; o > 0; o >>= 1) s += __shfl_xor_sync(0xffffffffu, s, o);
    if ((tid & 31) == 0) red[tid >> 5] = s;
    __syncthreads();
    float bs = 0.0f;
#pragma unroll
    for (int w = 0; w < 8; w++) bs += red[w];
    const float inv = 1.0f / bs;

#pragma unroll
    for (int i = 0; i < 8; i++) p[tid + i * 256] = e[i] * inv;
}

extern "C" void kernel_launch(void* const* d_in, const int* in_sizes, int n_in,
                              void* d_out, int out_size)
{
    const float* Q  = (const float*)d_in[0];
    const float* K  = (const float*)d_in[1];
    const float* V  = (const float*)d_in[2];
    const float* Wq = (const float*)d_in[3];
    const float* bq = (const float*)d_in[4];
    const float* Wk = (const float*)d_in[5];
    const float* bk = (const float*)d_in[6];
    const float* Wv = (const float*)d_in[7];
    const float* bv = (const float*)d_in[8];
    const float* Wo = (const float*)d_in[9];
    const float* bo = (const float*)d_in[10];

    float* out = (float*)d_out;

    const long long OUT_ELEMS  = (long long)BB * SS * DMODEL;           // 4,194,304
    const long long ATTN_ELEMS = (long long)BB * NHEADS * SS * SS;      // 67,108,864

    float *qp, *kp, *vp, *vtp, *ctxp, *attn_fb;
    cudaGetSymbolAddress((void**)&qp,      g_q);
    cudaGetSymbolAddress((void**)&kp,      g_k);
    cudaGetSymbolAddress((void**)&vp,      g_v);
    cudaGetSymbolAddress((void**)&vtp,     g_vt);
    cudaGetSymbolAddress((void**)&ctxp,    g_ctx);
    cudaGetSymbolAddress((void**)&attn_fb, g_attn_fallback);

    float* attn = ((long long)out_size >= OUT_ELEMS + ATTN_ELEMS)
                      ? (out + OUT_ELEMS) : attn_fb;

    cudaFuncSetAttribute(gemm_cp_kernel<true>,
                         cudaFuncAttributeMaxDynamicSharedMemorySize, GEMM_SMEM_BYTES);
    cudaFuncSetAttribute(gemm_cp_kernel<false>,
                         cudaFuncAttributeMaxDynamicSharedMemorySize, GEMM_SMEM_BYTES);

    const int M = BB * SS;   // 4096
    const float inv_sqrt_dk = 0.08838834764831845f;  // 1/sqrt(128)

    dim3 blk(256);

    // 1-3) projections: X @ W^T + b   [4096 x 1024], K=1024
    dim3 gProj(DMODEL / 128, M / 128, 1);
    gemm_cp_kernel<true><<<gProj, blk, GEMM_SMEM_BYTES>>>(Q, Wq, bq, qp,
        DMODEL, DMODEL, DMODEL, DMODEL, 1.0f, 1, 0, 0, 0, 0, 0, 0);
    gemm_cp_kernel<true><<<gProj, blk, GEMM_SMEM_BYTES>>>(K, Wk, bk, kp,
        DMODEL, DMODEL, DMODEL, DMODEL, 1.0f, 1, 0, 0, 0, 0, 0, 0);
    gemm_cp_kernel<true><<<gProj, blk, GEMM_SMEM_BYTES>>>(V, Wv, bv, vp,
        DMODEL, DMODEL, DMODEL, DMODEL, 1.0f, 1, 0, 0, 0, 0, 0, 0);

    // 3b) transpose V per head -> g_vt [(b,h)][n][s]
    {
        dim3 gT(SS / 32, DK / 32, BB * NHEADS);
        dim3 bT(32, 8);
        transpose_v_kernel<<<gT, bT>>>(vp, vtp);
    }

    // 4) scores = q @ k^T / sqrt(dk)  per (b,h): [2048 x 2048], K=128
    dim3 gScores(SS / 128, SS / 128, BB * NHEADS);
    gemm_cp_kernel<false><<<gScores, blk, GEMM_SMEM_BYTES>>>(qp, kp, nullptr, attn,
        DK, DMODEL, DMODEL, SS, inv_sqrt_dk,
        NHEADS,
        (long long)SS * DMODEL, (long long)DK,
        (long long)SS * DMODEL, (long long)DK,
        (long long)NHEADS * SS * SS, (long long)SS * SS);

    // 5) softmax over rows of attn
    softmax_kernel<<<BB * NHEADS * SS, blk>>>(attn);

    // 6) ctx = attn @ vt^T  per (b,h): [2048 x 128], K=2048
    dim3 gCtx(DK / 128, SS / 128, BB * NHEADS);
    gemm_cp_kernel<false><<<gCtx, blk, GEMM_SMEM_BYTES>>>(attn, vtp, nullptr, ctxp,
        SS, SS, SS, DMODEL, 1.0f,
        NHEADS,
        (long long)NHEADS * SS * SS, (long long)SS * SS,
        (long long)NHEADS * DK * SS, (long long)DK * SS,
        (long long)SS * DMODEL, (long long)DK);

    // 7) out = ctx @ Wo^T + bo   [4096 x 1024], K=1024
    gemm_cp_kernel<true><<<gProj, blk, GEMM_SMEM_BYTES>>>(ctxp, Wo, bo, out,
        DMODEL, DMODEL, DMODEL, DMODEL, 1.0f, 1, 0, 0, 0, 0, 0, 0);
}

// round 7
// speedup vs baseline: 3.1139x; 1.0074x over previous
#include <cuda_runtime.h>
#include <math.h>
#include <stdint.h>

#define DMODEL 1024
#define NHEADS 8
#define DK 128
#define BB 2
#define SS 2048
#define NZ (BB * NHEADS)          // 16
#define NTILE (SS / 128)          // 16

// Scratch (allocation-free rule: __device__ globals)
__device__ float g_q[(size_t)BB * SS * DMODEL];
__device__ float g_k[(size_t)BB * SS * DMODEL];
__device__ float g_v[(size_t)BB * SS * DMODEL];
__device__ float g_vt[(size_t)BB * NHEADS * DK * SS];
__device__ float g_ctx[(size_t)BB * SS * DMODEL];
__device__ float g_raw[(size_t)NZ * SS * SS];          // raw scaled scores
__device__ float g_statsM[(size_t)NZ * SS * NTILE];    // per-(row,tile) max
__device__ float g_statsS[(size_t)NZ * SS * NTILE];    // per-(row,tile) sum-exp
__device__ float g_rowM[(size_t)NZ * SS];
__device__ float g_rowInv[(size_t)NZ * SS];

__device__ __forceinline__ uint32_t smem_u32(const void* p) {
    uint32_t a;
    asm("{ .reg .u64 t; cvta.to.shared.u64 t, %1; cvt.u32.u64 %0, t; }" : "=r"(a) : "l"(p));
    return a;
}
__device__ __forceinline__ uint32_t f2tf32(float f) {
    uint32_t u;
    asm("cvt.rna.tf32.f32 %0, %1;" : "=r"(u) : "f"(f));
    return u;
}
__device__ __forceinline__ void mma_tf32(float* c, const uint32_t* a, const uint32_t* b) {
    asm volatile(
        "mma.sync.aligned.m16n8k8.row.col.f32.tf32.tf32.f32 "
        "{%0,%1,%2,%3},{%4,%5,%6,%7},{%8,%9},{%0,%1,%2,%3};"
        : "+f"(c[0]), "+f"(c[1]), "+f"(c[2]), "+f"(c[3])
        : "r"(a[0]), "r"(a[1]), "r"(a[2]), "r"(a[3]), "r"(b[0]), "r"(b[1]));
}
__device__ __forceinline__ void cp_async16(uint32_t saddr, const void* gaddr) {
    asm volatile("cp.async.cg.shared.global [%0], [%1], 16;"
                 :: "r"(saddr), "l"(gaddr) : "memory");
}
#define CP_COMMIT() asm volatile("cp.async.commit_group;" ::: "memory")
#define CP_WAIT2()  asm volatile("cp.async.wait_group 2;" ::: "memory")

// smem word index for (row m, k-word k) within a 128x16-word operand tile.
// XOR swizzle: conflict-free for 16B cp.async stores AND all mma fragment LDS.
// Preserves alignment of 4-word groups (XOR acts on k bits 2..3 only).
#define SW_WORD(m, k) ((uint32_t)(m) * 16u + ((uint32_t)(k) ^ (((((uint32_t)(m)) >> 1) & 3u) << 2)))

#define STAGE_BYTES 16384u           // A(8KB) + B(8KB)
#define GEMM_SMEM_BYTES 65536u       // 4 stages
#define CTX_SMEM_BYTES 66560u        // + rowM/rowInv cache (1KB)

// ============================================================================
// Generic batched TF32 GEMM (cp.async 4-stage):  C = alpha * A @ B^T + bias
// STATS: additionally emit per-tile row max / sum-exp (scores kernel only;
//        assumes 2048 rows per z and blockIdx.x < NTILE).
// ============================================================================
template <bool HAS_BIAS, bool STATS>
__global__ __launch_bounds__(256, 2) void gemm_cp_kernel(
    const float* __restrict__ A, const float* __restrict__ B,
    const float* __restrict__ bias, float* __restrict__ C,
    int K, int lda, int ldb, int ldc, float alpha,
    int Hdiv,
    long long sAb, long long sAh,
    long long sBb, long long sBh,
    long long sCb, long long sCh,
    float* __restrict__ statsM, float* __restrict__ statsS)
{
    extern __shared__ char smem[];
    const uint32_t sb = smem_u32(smem);

    const int z  = blockIdx.z;
    const int zb = z / Hdiv;
    const int zh = z % Hdiv;
    A += zb * sAb + zh * sAh;
    B += zb * sBb + zh * sBh;
    C += zb * sCb + zh * sCh;

    const int tid  = threadIdx.x;
    const int wid  = tid >> 5;
    const int lane = tid & 31;
    const int m0   = blockIdx.y * 128;
    const int n0   = blockIdx.x * 128;
    const int warp_m = wid >> 2;
    const int warp_n = wid & 3;
    const int grp  = lane >> 2;
    const int tig  = lane & 3;

    const int lm = tid >> 2;
    const int lc = (tid & 3) * 4;

    float acc[4][4][4];
#pragma unroll
    for (int i = 0; i < 4; i++)
#pragma unroll
        for (int j = 0; j < 4; j++)
#pragma unroll
            for (int q = 0; q < 4; q++) acc[i][j][q] = 0.0f;

#define ISSUE_BODY(bufi, k0)                                                    \
    {                                                                           \
        const uint32_t ab = sb + (uint32_t)(bufi) * STAGE_BYTES;                \
        const uint32_t bbs = ab + 8192u;                                        \
        _Pragma("unroll")                                                       \
        for (int i = 0; i < 2; i++) {                                           \
            const int m = lm + i * 64;                                          \
            cp_async16(ab + SW_WORD(m, lc) * 4u,                                \
                       A + (long long)(m0 + m) * lda + (k0) + lc);              \
            cp_async16(bbs + SW_WORD(m, lc) * 4u,                               \
                       B + (long long)(n0 + m) * ldb + (k0) + lc);              \
        }                                                                       \
    }

#define COMPUTE(bufi)                                                           \
    {                                                                           \
        const float* ab = reinterpret_cast<const float*>(                       \
            smem + (uint32_t)(bufi) * STAGE_BYTES);                             \
        const float* bbs = ab + 2048;                                           \
        _Pragma("unroll")                                                       \
        for (int ks = 0; ks < 2; ks++) {                                        \
            const int kb = ks * 8;                                              \
            uint32_t af[4][4], bf[4][2];                                        \
            _Pragma("unroll")                                                   \
            for (int mi = 0; mi < 4; mi++) {                                    \
                const int ra = warp_m * 64 + mi * 16 + grp;                     \
                af[mi][0] = f2tf32(ab[SW_WORD(ra,     kb + tig    )]);          \
                af[mi][1] = f2tf32(ab[SW_WORD(ra + 8, kb + tig    )]);          \
                af[mi][2] = f2tf32(ab[SW_WORD(ra,     kb + tig + 4)]);          \
                af[mi][3] = f2tf32(ab[SW_WORD(ra + 8, kb + tig + 4)]);          \
            }                                                                   \
            _Pragma("unroll")                                                   \
            for (int nj = 0; nj < 4; nj++) {                                    \
                const int nb = warp_n * 32 + nj * 8 + grp;                      \
                bf[nj][0] = f2tf32(bbs[SW_WORD(nb, kb + tig    )]);             \
                bf[nj][1] = f2tf32(bbs[SW_WORD(nb, kb + tig + 4)]);             \
            }                                                                   \
            _Pragma("unroll")                                                   \
            for (int mi = 0; mi < 4; mi++)                                      \
                _Pragma("unroll")                                               \
                for (int nj = 0; nj < 4; nj++)                                  \
                    mma_tf32(acc[mi][nj], af[mi], bf[nj]);                      \
        }                                                                       \
    }

    const int S = K >> 4;

    ISSUE_BODY(0, 0)   CP_COMMIT();
    ISSUE_BODY(1, 16)  CP_COMMIT();
    ISSUE_BODY(2, 32)  CP_COMMIT();

    for (int s = 0; s < S; s++) {
        CP_WAIT2();
        __syncthreads();
        COMPUTE(s & 3)
        if (s + 3 < S) {
            ISSUE_BODY((s + 3) & 3, (s + 3) * 16)
        }
        CP_COMMIT();   // unconditional: exact wait_group accounting in the tail
    }

    // ---- write C ----
#pragma unroll
    for (int nj = 0; nj < 4; nj++) {
        const int cc = n0 + warp_n * 32 + nj * 8 + tig * 2;
        float b0 = 0.0f, b1 = 0.0f;
        if (HAS_BIAS) { b0 = bias[cc]; b1 = bias[cc + 1]; }
#pragma unroll
        for (int mi = 0; mi < 4; mi++) {
            const long long r0 = m0 + warp_m * 64 + mi * 16 + grp;
            const long long r1 = r0 + 8;
            float2 v0, v1;
            v0.x = alpha * acc[mi][nj][0] + b0;
            v0.y = alpha * acc[mi][nj][1] + b1;
            v1.x = alpha * acc[mi][nj][2] + b0;
            v1.y = alpha * acc[mi][nj][3] + b1;
            *reinterpret_cast<float2*>(C + r0 * ldc + cc) = v0;
            *reinterpret_cast<float2*>(C + r1 * ldc + cc) = v1;
        }
    }

    // ---- per-tile softmax stats (scores only) ----
    if (STATS) {
        __syncthreads();   // pipeline smem reuse
        float* sred    = reinterpret_cast<float*>(smem);          // [4][128]
        float* rowmaxs = reinterpret_cast<float*>(smem) + 512;    // [128]

        // pass 1: per-row tile max
#pragma unroll
        for (int mi = 0; mi < 4; mi++) {
#pragma unroll
            for (int h = 0; h < 2; h++) {
                float mx = -1e30f;
#pragma unroll
                for (int nj = 0; nj < 4; nj++)
                    mx = fmaxf(mx, fmaxf(alpha * acc[mi][nj][h * 2],
                                         alpha * acc[mi][nj][h * 2 + 1]));
                mx = fmaxf(mx, __shfl_xor_sync(0xffffffffu, mx, 1));
                mx = fmaxf(mx, __shfl_xor_sync(0xffffffffu, mx, 2));
                const int rl = warp_m * 64 + mi * 16 + grp + h * 8;
                if (tig == 0) sred[warp_n * 128 + rl] = mx;
            }
        }
        __syncthreads();
        if (tid < 128) {
            float rm = fmaxf(fmaxf(sred[tid], sred[128 + tid]),
                             fmaxf(sred[256 + tid], sred[384 + tid]));
            rowmaxs[tid] = rm;
        }
        __syncthreads();

        // pass 2: per-row tile sum of exp
#pragma unroll
        for (int mi = 0; mi < 4; mi++) {
#pragma unroll
            for (int h = 0; h < 2; h++) {
                const int rl = warp_m * 64 + mi * 16 + grp + h * 8;
                const float rm = rowmaxs[rl];
                float s = 0.0f;
#pragma unroll
                for (int nj = 0; nj < 4; nj++) {
                    s += __expf(alpha * acc[mi][nj][h * 2]     - rm);
                    s += __expf(alpha * acc[mi][nj][h * 2 + 1] - rm);
                }
                s += __shfl_xor_sync(0xffffffffu, s, 1);
                s += __shfl_xor_sync(0xffffffffu, s, 2);
                if (tig == 0) sred[warp_n * 128 + rl] = s;
            }
        }
        __syncthreads();
        if (tid < 128) {
            const float sg = sred[tid] + sred[128 + tid] + sred[256 + tid] + sred[384 + tid];
            const long long gi = ((long long)z * SS + m0 + tid) * NTILE + blockIdx.x;
            statsM[gi] = rowmaxs[tid];
            statsS[gi] = sg;
        }
    }
#undef ISSUE_BODY
#undef COMPUTE
}

// ============================================================================
// Combine per-tile stats into global row max + inverse sum.
// ============================================================================
__global__ __launch_bounds__(256) void combine_stats_kernel(
    const float* __restrict__ sM, const float* __restrict__ sS,
    float* __restrict__ rowM, float* __restrict__ rowInv)
{
    const long long r = (long long)blockIdx.x * 256 + threadIdx.x;  // 0..32767
    const float* pm = sM + r * NTILE;
    const float* ps = sS + r * NTILE;
    float M = -1e30f;
#pragma unroll
    for (int t = 0; t < NTILE; t++) M = fmaxf(M, pm[t]);
    float S = 0.0f;
#pragma unroll
    for (int t = 0; t < NTILE; t++) S += ps[t] * __expf(pm[t] - M);
    rowM[r]   = M;
    rowInv[r] = 1.0f / S;
}

// ============================================================================
// Fused softmax + ctx GEMM.
//   A = raw scores [z][2048][2048]; per-stage transform p=exp(s-M)*inv is
//   written back to smem (mma input) and STG'd to the attn output.
//   B = vt [z][128 dk][2048 s].  C = ctx [b*S+s][h*128+dk].
// ============================================================================
__global__ __launch_bounds__(256, 2) void ctx_fused_kernel(
    const float* __restrict__ RAW, const float* __restrict__ VT,
    float* __restrict__ CTX, float* __restrict__ ATTN,
    const float* __restrict__ rowM, const float* __restrict__ rowInv)
{
    extern __shared__ char smem[];
    const uint32_t sb = smem_u32(smem);
    float* sM_s = reinterpret_cast<float*>(smem + GEMM_SMEM_BYTES);        // [128]
    float* sI_s = sM_s + 128;                                              // [128]

    const int z  = blockIdx.z;
    const int zb = z >> 3;
    const int zh = z & 7;
    const float* A = RAW + (long long)z * SS * SS;
    const float* B = VT + (long long)z * DK * SS;
    float* C = CTX + (long long)zb * SS * DMODEL + (long long)zh * DK;
    float* AT = ATTN + (long long)z * SS * SS;

    const int tid  = threadIdx.x;
    const int wid  = tid >> 5;
    const int lane = tid & 31;
    const int m0   = blockIdx.y * 128;
    const int warp_m = wid >> 2;
    const int warp_n = wid & 3;
    const int grp  = lane >> 2;
    const int tig  = lane & 3;

    const int lm = tid >> 2;
    const int lc = (tid & 3) * 4;

    if (tid < 128) {
        sM_s[tid] = rowM[(long long)z * SS + m0 + tid];
        sI_s[tid] = rowInv[(long long)z * SS + m0 + tid];
    }

    float acc[4][4][4];
#pragma unroll
    for (int i = 0; i < 4; i++)
#pragma unroll
        for (int j = 0; j < 4; j++)
#pragma unroll
            for (int q = 0; q < 4; q++) acc[i][j][q] = 0.0f;

#define ISSUE_BODY(bufi, k0)                                                    \
    {                                                                           \
        const uint32_t ab = sb + (uint32_t)(bufi) * STAGE_BYTES;                \
        const uint32_t bbs = ab + 8192u;                                        \
        _Pragma("unroll")                                                       \
        for (int i = 0; i < 2; i++) {                                           \
            const int m = lm + i * 64;                                          \
            cp_async16(ab + SW_WORD(m, lc) * 4u,                                \
                       A + (long long)(m0 + m) * SS + (k0) + lc);               \
            cp_async16(bbs + SW_WORD(m, lc) * 4u,                               \
                       B + (long long)m * SS + (k0) + lc);                      \
        }                                                                       \
    }

    // transform raw scores tile in smem -> probabilities; also STG to attn
#define TRANSFORM(bufi, k0)                                                     \
    {                                                                           \
        float* ab = reinterpret_cast<float*>(smem + (uint32_t)(bufi) * STAGE_BYTES); \
        _Pragma("unroll")                                                       \
        for (int i = 0; i < 2; i++) {                                           \
            const int m = (tid >> 2) + i * 64;                                  \
            const int kg = (tid & 3) * 4;                                       \
            const float rm = sM_s[m], ri = sI_s[m];                             \
            float4* p = reinterpret_cast<float4*>(&ab[SW_WORD(m, kg)]);         \
            float4 v = *p;                                                      \
            v.x = __expf(v.x - rm) * ri;                                        \
            v.y = __expf(v.y - rm) * ri;                                        \
            v.z = __expf(v.z - rm) * ri;                                        \
            v.w = __expf(v.w - rm) * ri;                                        \
            *p = v;                                                             \
            *reinterpret_cast<float4*>(AT + (long long)(m0 + m) * SS + (k0) + kg) = v; \
        }                                                                       \
    }

#define COMPUTE(bufi)                                                           \
    {                                                                           \
        const float* ab = reinterpret_cast<const float*>(                       \
            smem + (uint32_t)(bufi) * STAGE_BYTES);                             \
        const float* bbs = ab + 2048;                                           \
        _Pragma("unroll")                                                       \
        for (int ks = 0; ks < 2; ks++) {                                        \
            const int kb = ks * 8;                                              \
            uint32_t af[4][4], bf[4][2];                                        \
            _Pragma("unroll")                                                   \
            for (int mi = 0; mi < 4; mi++) {                                    \
                const int ra = warp_m * 64 + mi * 16 + grp;                     \
                af[mi][0] = f2tf32(ab[SW_WORD(ra,     kb + tig    )]);          \
                af[mi][1] = f2tf32(ab[SW_WORD(ra + 8, kb + tig    )]);          \
                af[mi][2] = f2tf32(ab[SW_WORD(ra,     kb + tig + 4)]);          \
                af[mi][3] = f2tf32(ab[SW_WORD(ra + 8, kb + tig + 4)]);          \
            }                                                                   \
            _Pragma("unroll")                                                   \
            for (int nj = 0; nj < 4; nj++) {                                    \
                const int nb = warp_n * 32 + nj * 8 + grp;                      \
                bf[nj][0] = f2tf32(bbs[SW_WORD(nb, kb + tig    )]);             \
                bf[nj][1] = f2tf32(bbs[SW_WORD(nb, kb + tig + 4)]);             \
            }                                                                   \
            _Pragma("unroll")                                                   \
            for (int mi = 0; mi < 4; mi++)                                      \
                _Pragma("unroll")                                               \
                for (int nj = 0; nj < 4; nj++)                                  \
                    mma_tf32(acc[mi][nj], af[mi], bf[nj]);                      \
        }                                                                       \
    }

    const int S = SS >> 4;   // 128 stages

    ISSUE_BODY(0, 0)   CP_COMMIT();
    ISSUE_BODY(1, 16)  CP_COMMIT();
    ISSUE_BODY(2, 32)  CP_COMMIT();

    for (int s = 0; s < S; s++) {
        CP_WAIT2();
        __syncthreads();
        TRANSFORM(s & 3, s * 16)
        __syncthreads();
        COMPUTE(s & 3)
        if (s + 3 < S) {
            ISSUE_BODY((s + 3) & 3, (s + 3) * 16)
        }
        CP_COMMIT();
    }

    // ---- write ctx ----
#pragma unroll
    for (int nj = 0; nj < 4; nj++) {
        const int cc = warp_n * 32 + nj * 8 + tig * 2;
#pragma unroll
        for (int mi = 0; mi < 4; mi++) {
            const long long r0 = m0 + warp_m * 64 + mi * 16 + grp;
            const long long r1 = r0 + 8;
            float2 v0, v1;
            v0.x = acc[mi][nj][0];
            v0.y = acc[mi][nj][1];
            v1.x = acc[mi][nj][2];
            v1.y = acc[mi][nj][3];
            *reinterpret_cast<float2*>(C + r0 * DMODEL + cc) = v0;
            *reinterpret_cast<float2*>(C + r1 * DMODEL + cc) = v1;
        }
    }
#undef ISSUE_BODY
#undef TRANSFORM
#undef COMPUTE
}

// ----------------------------------------------------------------------------
// V transpose: g_v [(b*S+s)][h*128+n]  ->  g_vt [((b*8+h)*128+n)][s]
// ----------------------------------------------------------------------------
__global__ void transpose_v_kernel(const float* __restrict__ v, float* __restrict__ vt)
{
    __shared__ float t[32][33];
    const int z = blockIdx.z, b = z >> 3, h = z & 7;
    const int s0 = blockIdx.x * 32, n0 = blockIdx.y * 32;
    const int tx = threadIdx.x, ty = threadIdx.y;
#pragma unroll
    for (int j = ty; j < 32; j += 8)
        t[j][tx] = v[((long long)b * SS + s0 + j) * DMODEL + h * DK + n0 + tx];
    __syncthreads();
#pragma unroll
    for (int j = ty; j < 32; j += 8)
        vt[((long long)z * DK + n0 + j) * SS + s0 + tx] = t[tx][j];
}

extern "C" void kernel_launch(void* const* d_in, const int* in_sizes, int n_in,
                              void* d_out, int out_size)
{
    const float* Q  = (const float*)d_in[0];
    const float* K  = (const float*)d_in[1];
    const float* V  = (const float*)d_in[2];
    const float* Wq = (const float*)d_in[3];
    const float* bq = (const float*)d_in[4];
    const float* Wk = (const float*)d_in[5];
    const float* bk = (const float*)d_in[6];
    const float* Wv = (const float*)d_in[7];
    const float* bv = (const float*)d_in[8];
    const float* Wo = (const float*)d_in[9];
    const float* bo = (const float*)d_in[10];

    float* out = (float*)d_out;

    const long long OUT_ELEMS  = (long long)BB * SS * DMODEL;
    const long long ATTN_ELEMS = (long long)NZ * SS * SS;

    float *qp, *kp, *vp, *vtp, *ctxp, *rawp, *sMp, *sSp, *rMp, *rIp;
    cudaGetSymbolAddress((void**)&qp,   g_q);
    cudaGetSymbolAddress((void**)&kp,   g_k);
    cudaGetSymbolAddress((void**)&vp,   g_v);
    cudaGetSymbolAddress((void**)&vtp,  g_vt);
    cudaGetSymbolAddress((void**)&ctxp, g_ctx);
    cudaGetSymbolAddress((void**)&rawp, g_raw);
    cudaGetSymbolAddress((void**)&sMp,  g_statsM);
    cudaGetSymbolAddress((void**)&sSp,  g_statsS);
    cudaGetSymbolAddress((void**)&rMp,  g_rowM);
    cudaGetSymbolAddress((void**)&rIp,  g_rowInv);

    // final attn destination (tuple layout [out | attn]); fallback aliases raw,
    // which is safe: each raw location is consumed (cp.async) before the fused
    // kernel overwrites it in the same CTA stage.
    float* attn = ((long long)out_size >= OUT_ELEMS + ATTN_ELEMS)
                      ? (out + OUT_ELEMS) : rawp;

    cudaFuncSetAttribute(gemm_cp_kernel<true, false>,
                         cudaFuncAttributeMaxDynamicSharedMemorySize, GEMM_SMEM_BYTES);
    cudaFuncSetAttribute(gemm_cp_kernel<false, true>,
                         cudaFuncAttributeMaxDynamicSharedMemorySize, GEMM_SMEM_BYTES);
    cudaFuncSetAttribute(ctx_fused_kernel,
                         cudaFuncAttributeMaxDynamicSharedMemorySize, CTX_SMEM_BYTES);

    const int M = BB * SS;
    const float inv_sqrt_dk = 0.08838834764831845f;

    dim3 blk(256);

    // 1-3) projections: X @ W^T + b   [4096 x 1024], K=1024
    dim3 gProj(DMODEL / 128, M / 128, 1);
    gemm_cp_kernel<true, false><<<gProj, blk, GEMM_SMEM_BYTES>>>(Q, Wq, bq, qp,
        DMODEL, DMODEL, DMODEL, DMODEL, 1.0f, 1, 0, 0, 0, 0, 0, 0, nullptr, nullptr);
    gemm_cp_kernel<true, false><<<gProj, blk, GEMM_SMEM_BYTES>>>(K, Wk, bk, kp,
        DMODEL, DMODEL, DMODEL, DMODEL, 1.0f, 1, 0, 0, 0, 0, 0, 0, nullptr, nullptr);
    gemm_cp_kernel<true, false><<<gProj, blk, GEMM_SMEM_BYTES>>>(V, Wv, bv, vp,
        DMODEL, DMODEL, DMODEL, DMODEL, 1.0f, 1, 0, 0, 0, 0, 0, 0, nullptr, nullptr);

    // 3b) transpose V per head -> g_vt [(b,h)][n][s]
    {
        dim3 gT(SS / 32, DK / 32, NZ);
        dim3 bT(32, 8);
        transpose_v_kernel<<<gT, bT>>>(vp, vtp);
    }

    // 4) raw scores = q @ k^T / sqrt(dk), with per-tile softmax stats
    dim3 gScores(SS / 128, SS / 128, NZ);
    gemm_cp_kernel<false, true><<<gScores, blk, GEMM_SMEM_BYTES>>>(qp, kp, nullptr, rawp,
        DK, DMODEL, DMODEL, SS, inv_sqrt_dk,
        NHEADS,
        (long long)SS * DMODEL, (long long)DK,
        (long long)SS * DMODEL, (long long)DK,
        (long long)NHEADS * SS * SS, (long long)SS * SS,
        sMp, sSp);

    // 5) combine stats -> rowM, rowInv
    combine_stats_kernel<<<(NZ * SS) / 256, blk>>>(sMp, sSp, rMp, rIp);

    // 6) fused softmax + ctx GEMM (+ attn output write)
    {
        dim3 gCtx(1, SS / 128, NZ);
        ctx_fused_kernel<<<gCtx, blk, CTX_SMEM_BYTES>>>(rawp, vtp, ctxp, attn, rMp, rIp);
    }

    // 7) out = ctx @ Wo^T + bo   [4096 x 1024], K=1024
    gemm_cp_kernel<true, false><<<gProj, blk, GEMM_SMEM_BYTES>>>(ctxp, Wo, bo, out,
        DMODEL, DMODEL, DMODEL, DMODEL, 1.0f, 1, 0, 0, 0, 0, 0, 0, nullptr, nullptr);
}

// round 8
// speedup vs baseline: 3.4119x; 1.0957x over previous
#include <cuda_runtime.h>
#include <math.h>
#include <stdint.h>

#define DMODEL 1024
#define NHEADS 8
#define DK 128
#define BB 2
#define SS 2048
#define NZ (BB * NHEADS)          // 16
#define NTILE (SS / 128)          // 16

// Scratch (allocation-free rule: __device__ globals)
__device__ float g_q[(size_t)BB * SS * DMODEL];
__device__ float g_k[(size_t)BB * SS * DMODEL];
__device__ float g_v[(size_t)BB * SS * DMODEL];
__device__ float g_vt[(size_t)BB * NHEADS * DK * SS];
__device__ float g_ctx[(size_t)BB * SS * DMODEL];
__device__ float g_raw[(size_t)NZ * SS * SS];          // raw scaled scores
__device__ float g_statsM[(size_t)NZ * SS * NTILE];
__device__ float g_statsS[(size_t)NZ * SS * NTILE];
__device__ float g_rowM[(size_t)NZ * SS];
__device__ float g_rowInv[(size_t)NZ * SS];
__device__ float g_w[4][(size_t)DMODEL * DMODEL];      // tf32-rounded weights

__device__ __forceinline__ uint32_t smem_u32(const void* p) {
    uint32_t a;
    asm("{ .reg .u64 t; cvta.to.shared.u64 t, %1; cvt.u32.u64 %0, t; }" : "=r"(a) : "l"(p));
    return a;
}
__device__ __forceinline__ uint32_t f2tf32(float f) {
    uint32_t u;
    asm("cvt.rna.tf32.f32 %0, %1;" : "=r"(u) : "f"(f));
    return u;
}
__device__ __forceinline__ float rnd_tf32(float f) {
    return __uint_as_float(f2tf32(f));
}
__device__ __forceinline__ void mma_tf32(float* c, const uint32_t* a, const uint32_t* b) {
    asm volatile(
        "mma.sync.aligned.m16n8k8.row.col.f32.tf32.tf32.f32 "
        "{%0,%1,%2,%3},{%4,%5,%6,%7},{%8,%9},{%0,%1,%2,%3};"
        : "+f"(c[0]), "+f"(c[1]), "+f"(c[2]), "+f"(c[3])
        : "r"(a[0]), "r"(a[1]), "r"(a[2]), "r"(a[3]), "r"(b[0]), "r"(b[1]));
}
__device__ __forceinline__ void cp_async16(uint32_t saddr, const void* gaddr) {
    asm volatile("cp.async.cg.shared.global [%0], [%1], 16;"
                 :: "r"(saddr), "l"(gaddr) : "memory");
}
#define CP_COMMIT() asm volatile("cp.async.commit_group;" ::: "memory")
#define CP_WAIT2()  asm volatile("cp.async.wait_group 2;" ::: "memory")

// smem word index for (row m, k-word k) within a 128x16-word operand tile.
// XOR swizzle: conflict-free for 16B cp.async stores AND all mma fragment LDS.
#define SW_WORD(m, k) ((uint32_t)(m) * 16u + ((uint32_t)(k) ^ (((((uint32_t)(m)) >> 1) & 3u) << 2)))

#define STAGE_BYTES 16384u
#define GEMM_SMEM_BYTES 65536u
#define CTX_SMEM_BYTES 66560u

// ============================================================================
// Generic batched TF32 GEMM (cp.async 4-stage):  C = alpha * A @ B^T + bias
//   CVT_A / CVT_B: apply cvt.rna.tf32 at fragment load (false => operand is
//   already tf32-rounded in memory). ROUND_OUT: round C to tf32 before STG.
//   STATS: emit per-tile softmax row stats (scores kernel).
// ============================================================================
template <bool HAS_BIAS, bool STATS, bool CVT_A, bool CVT_B, bool ROUND_OUT>
__global__ __launch_bounds__(256, 2) void gemm_cp_kernel(
    const float* __restrict__ A, const float* __restrict__ B,
    const float* __restrict__ bias, float* __restrict__ C,
    int K, int lda, int ldb, int ldc, float alpha,
    int Hdiv,
    long long sAb, long long sAh,
    long long sBb, long long sBh,
    long long sCb, long long sCh,
    float* __restrict__ statsM, float* __restrict__ statsS)
{
    extern __shared__ char smem[];
    const uint32_t sb = smem_u32(smem);

    const int z  = blockIdx.z;
    const int zb = z / Hdiv;
    const int zh = z % Hdiv;
    A += zb * sAb + zh * sAh;
    B += zb * sBb + zh * sBh;
    C += zb * sCb + zh * sCh;

    const int tid  = threadIdx.x;
    const int wid  = tid >> 5;
    const int lane = tid & 31;
    const int m0   = blockIdx.y * 128;
    const int n0   = blockIdx.x * 128;
    const int warp_m = wid >> 2;
    const int warp_n = wid & 3;
    const int grp  = lane >> 2;
    const int tig  = lane & 3;

    const int lm = tid >> 2;
    const int lc = (tid & 3) * 4;

    float acc[4][4][4];
#pragma unroll
    for (int i = 0; i < 4; i++)
#pragma unroll
        for (int j = 0; j < 4; j++)
#pragma unroll
            for (int q = 0; q < 4; q++) acc[i][j][q] = 0.0f;

#define ISSUE_BODY(bufi, k0)                                                    \
    {                                                                           \
        const uint32_t ab = sb + (uint32_t)(bufi) * STAGE_BYTES;                \
        const uint32_t bbs = ab + 8192u;                                        \
        _Pragma("unroll")                                                       \
        for (int i = 0; i < 2; i++) {                                           \
            const int m = lm + i * 64;                                          \
            cp_async16(ab + SW_WORD(m, lc) * 4u,                                \
                       A + (long long)(m0 + m) * lda + (k0) + lc);              \
            cp_async16(bbs + SW_WORD(m, lc) * 4u,                               \
                       B + (long long)(n0 + m) * ldb + (k0) + lc);              \
        }                                                                       \
    }

#define FRAG_A(x) (CVT_A ? f2tf32(x) : __float_as_uint(x))
#define FRAG_B(x) (CVT_B ? f2tf32(x) : __float_as_uint(x))

#define COMPUTE(bufi)                                                           \
    {                                                                           \
        const float* ab = reinterpret_cast<const float*>(                       \
            smem + (uint32_t)(bufi) * STAGE_BYTES);                             \
        const float* bbs = ab + 2048;                                           \
        _Pragma("unroll")                                                       \
        for (int ks = 0; ks < 2; ks++) {                                        \
            const int kb = ks * 8;                                              \
            uint32_t af[4][4], bf[4][2];                                        \
            _Pragma("unroll")                                                   \
            for (int mi = 0; mi < 4; mi++) {                                    \
                const int ra = warp_m * 64 + mi * 16 + grp;                     \
                af[mi][0] = FRAG_A(ab[SW_WORD(ra,     kb + tig    )]);          \
                af[mi][1] = FRAG_A(ab[SW_WORD(ra + 8, kb + tig    )]);          \
                af[mi][2] = FRAG_A(ab[SW_WORD(ra,     kb + tig + 4)]);          \
                af[mi][3] = FRAG_A(ab[SW_WORD(ra + 8, kb + tig + 4)]);          \
            }                                                                   \
            _Pragma("unroll")                                                   \
            for (int nj = 0; nj < 4; nj++) {                                    \
                const int nb = warp_n * 32 + nj * 8 + grp;                      \
                bf[nj][0] = FRAG_B(bbs[SW_WORD(nb, kb + tig    )]);             \
                bf[nj][1] = FRAG_B(bbs[SW_WORD(nb, kb + tig + 4)]);             \
            }                                                                   \
            _Pragma("unroll")                                                   \
            for (int mi = 0; mi < 4; mi++)                                      \
                _Pragma("unroll")                                               \
                for (int nj = 0; nj < 4; nj++)                                  \
                    mma_tf32(acc[mi][nj], af[mi], bf[nj]);                      \
        }                                                                       \
    }

    const int S = K >> 4;

    ISSUE_BODY(0, 0)   CP_COMMIT();
    ISSUE_BODY(1, 16)  CP_COMMIT();
    ISSUE_BODY(2, 32)  CP_COMMIT();

    for (int s = 0; s < S; s++) {
        CP_WAIT2();
        __syncthreads();
        COMPUTE(s & 3)
        if (s + 3 < S) {
            ISSUE_BODY((s + 3) & 3, (s + 3) * 16)
        }
        CP_COMMIT();   // unconditional: exact wait_group accounting in the tail
    }

    // ---- write C ----
#pragma unroll
    for (int nj = 0; nj < 4; nj++) {
        const int cc = n0 + warp_n * 32 + nj * 8 + tig * 2;
        float b0 = 0.0f, b1 = 0.0f;
        if (HAS_BIAS) { b0 = bias[cc]; b1 = bias[cc + 1]; }
#pragma unroll
        for (int mi = 0; mi < 4; mi++) {
            const long long r0 = m0 + warp_m * 64 + mi * 16 + grp;
            const long long r1 = r0 + 8;
            float2 v0, v1;
            v0.x = alpha * acc[mi][nj][0] + b0;
            v0.y = alpha * acc[mi][nj][1] + b1;
            v1.x = alpha * acc[mi][nj][2] + b0;
            v1.y = alpha * acc[mi][nj][3] + b1;
            if (ROUND_OUT) {
                v0.x = rnd_tf32(v0.x); v0.y = rnd_tf32(v0.y);
                v1.x = rnd_tf32(v1.x); v1.y = rnd_tf32(v1.y);
            }
            *reinterpret_cast<float2*>(C + r0 * ldc + cc) = v0;
            *reinterpret_cast<float2*>(C + r1 * ldc + cc) = v1;
        }
    }

    // ---- per-tile softmax stats (scores only) ----
    if (STATS) {
        __syncthreads();
        float* sred    = reinterpret_cast<float*>(smem);          // [4][128]
        float* rowmaxs = reinterpret_cast<float*>(smem) + 512;    // [128]

#pragma unroll
        for (int mi = 0; mi < 4; mi++) {
#pragma unroll
            for (int h = 0; h < 2; h++) {
                float mx = -1e30f;
#pragma unroll
                for (int nj = 0; nj < 4; nj++)
                    mx = fmaxf(mx, fmaxf(alpha * acc[mi][nj][h * 2],
                                         alpha * acc[mi][nj][h * 2 + 1]));
                mx = fmaxf(mx, __shfl_xor_sync(0xffffffffu, mx, 1));
                mx = fmaxf(mx, __shfl_xor_sync(0xffffffffu, mx, 2));
                const int rl = warp_m * 64 + mi * 16 + grp + h * 8;
                if (tig == 0) sred[warp_n * 128 + rl] = mx;
            }
        }
        __syncthreads();
        if (tid < 128) {
            float rm = fmaxf(fmaxf(sred[tid], sred[128 + tid]),
                             fmaxf(sred[256 + tid], sred[384 + tid]));
            rowmaxs[tid] = rm;
        }
        __syncthreads();

#pragma unroll
        for (int mi = 0; mi < 4; mi++) {
#pragma unroll
            for (int h = 0; h < 2; h++) {
                const int rl = warp_m * 64 + mi * 16 + grp + h * 8;
                const float rm = rowmaxs[rl];
                float s = 0.0f;
#pragma unroll
                for (int nj = 0; nj < 4; nj++) {
                    s += __expf(alpha * acc[mi][nj][h * 2]     - rm);
                    s += __expf(alpha * acc[mi][nj][h * 2 + 1] - rm);
                }
                s += __shfl_xor_sync(0xffffffffu, s, 1);
                s += __shfl_xor_sync(0xffffffffu, s, 2);
                if (tig == 0) sred[warp_n * 128 + rl] = s;
            }
        }
        __syncthreads();
        if (tid < 128) {
            const float sg = sred[tid] + sred[128 + tid] + sred[256 + tid] + sred[384 + tid];
            const long long gi = ((long long)z * SS + m0 + tid) * NTILE + blockIdx.x;
            statsM[gi] = rowmaxs[tid];
            statsS[gi] = sg;
        }
    }
#undef ISSUE_BODY
#undef COMPUTE
#undef FRAG_A
#undef FRAG_B
}

// ============================================================================
// Round weight matrices to tf32 (prepass). grid.z selects the matrix.
// ============================================================================
__global__ __launch_bounds__(256) void round_weights_kernel(
    const float* __restrict__ w0, const float* __restrict__ w1,
    const float* __restrict__ w2, const float* __restrict__ w3,
    float* __restrict__ dst)   // g_w base; [4][D*D]
{
    const float* src = (blockIdx.z == 0) ? w0 : (blockIdx.z == 1) ? w1
                     : (blockIdx.z == 2) ? w2 : w3;
    float* d = dst + (size_t)blockIdx.z * DMODEL * DMODEL;
    const long long i = ((long long)blockIdx.x * 256 + threadIdx.x) * 4;
    float4 v = *reinterpret_cast<const float4*>(src + i);
    v.x = rnd_tf32(v.x); v.y = rnd_tf32(v.y);
    v.z = rnd_tf32(v.z); v.w = rnd_tf32(v.w);
    *reinterpret_cast<float4*>(d + i) = v;
}

// ============================================================================
// Combine per-tile stats into global row max + inverse sum.
// ============================================================================
__global__ __launch_bounds__(256) void combine_stats_kernel(
    const float* __restrict__ sM, const float* __restrict__ sS,
    float* __restrict__ rowM, float* __restrict__ rowInv)
{
    const long long r = (long long)blockIdx.x * 256 + threadIdx.x;
    const float* pm = sM + r * NTILE;
    const float* ps = sS + r * NTILE;
    float M = -1e30f;
#pragma unroll
    for (int t = 0; t < NTILE; t++) M = fmaxf(M, pm[t]);
    float S = 0.0f;
#pragma unroll
    for (int t = 0; t < NTILE; t++) S += ps[t] * __expf(pm[t] - M);
    rowM[r]   = M;
    rowInv[r] = 1.0f / S;
}

// ============================================================================
// Fused softmax + ctx GEMM. Transform writes fp32 p to attn output and
// tf32-rounded p back to smem (mma A operand). All fragment loads cvt-free.
// ctx output rounded to tf32 (feeds out-projection).
// ============================================================================
__global__ __launch_bounds__(256, 2) void ctx_fused_kernel(
    const float* __restrict__ RAW, const float* __restrict__ VT,
    float* __restrict__ CTX, float* __restrict__ ATTN,
    const float* __restrict__ rowM, const float* __restrict__ rowInv)
{
    extern __shared__ char smem[];
    const uint32_t sb = smem_u32(smem);
    float* sM_s = reinterpret_cast<float*>(smem + GEMM_SMEM_BYTES);
    float* sI_s = sM_s + 128;

    const int z  = blockIdx.z;
    const int zb = z >> 3;
    const int zh = z & 7;
    const float* A = RAW + (long long)z * SS * SS;
    const float* B = VT + (long long)z * DK * SS;
    float* C = CTX + (long long)zb * SS * DMODEL + (long long)zh * DK;
    float* AT = ATTN + (long long)z * SS * SS;

    const int tid  = threadIdx.x;
    const int wid  = tid >> 5;
    const int lane = tid & 31;
    const int m0   = blockIdx.y * 128;
    const int warp_m = wid >> 2;
    const int warp_n = wid & 3;
    const int grp  = lane >> 2;
    const int tig  = lane & 3;

    const int lm = tid >> 2;
    const int lc = (tid & 3) * 4;

    if (tid < 128) {
        sM_s[tid] = rowM[(long long)z * SS + m0 + tid];
        sI_s[tid] = rowInv[(long long)z * SS + m0 + tid];
    }

    float acc[4][4][4];
#pragma unroll
    for (int i = 0; i < 4; i++)
#pragma unroll
        for (int j = 0; j < 4; j++)
#pragma unroll
            for (int q = 0; q < 4; q++) acc[i][j][q] = 0.0f;

#define ISSUE_BODY(bufi, k0)                                                    \
    {                                                                           \
        const uint32_t ab = sb + (uint32_t)(bufi) * STAGE_BYTES;                \
        const uint32_t bbs = ab + 8192u;                                        \
        _Pragma("unroll")                                                       \
        for (int i = 0; i < 2; i++) {                                           \
            const int m = lm + i * 64;                                          \
            cp_async16(ab + SW_WORD(m, lc) * 4u,                                \
                       A + (long long)(m0 + m) * SS + (k0) + lc);               \
            cp_async16(bbs + SW_WORD(m, lc) * 4u,                               \
                       B + (long long)m * SS + (k0) + lc);                      \
        }                                                                       \
    }

#define TRANSFORM(bufi, k0)                                                     \
    {                                                                           \
        float* ab = reinterpret_cast<float*>(smem + (uint32_t)(bufi) * STAGE_BYTES); \
        _Pragma("unroll")                                                       \
        for (int i = 0; i < 2; i++) {                                           \
            const int m = (tid >> 2) + i * 64;                                  \
            const int kg = (tid & 3) * 4;                                       \
            const float rm = sM_s[m], ri = sI_s[m];                             \
            float4* p = reinterpret_cast<float4*>(&ab[SW_WORD(m, kg)]);         \
            float4 v = *p;                                                      \
            v.x = __expf(v.x - rm) * ri;                                        \
            v.y = __expf(v.y - rm) * ri;                                        \
            v.z = __expf(v.z - rm) * ri;                                        \
            v.w = __expf(v.w - rm) * ri;                                        \
            *reinterpret_cast<float4*>(AT + (long long)(m0 + m) * SS + (k0) + kg) = v; \
            float4 r4;                                                          \
            r4.x = rnd_tf32(v.x); r4.y = rnd_tf32(v.y);                         \
            r4.z = rnd_tf32(v.z); r4.w = rnd_tf32(v.w);                         \
            *p = r4;                                                            \
        }                                                                       \
    }

#define COMPUTE(bufi)                                                           \
    {                                                                           \
        const float* ab = reinterpret_cast<const float*>(                       \
            smem + (uint32_t)(bufi) * STAGE_BYTES);                             \
        const float* bbs = ab + 2048;                                           \
        _Pragma("unroll")                                                       \
        for (int ks = 0; ks < 2; ks++) {                                        \
            const int kb = ks * 8;                                              \
            uint32_t af[4][4], bf[4][2];                                        \
            _Pragma("unroll")                                                   \
            for (int mi = 0; mi < 4; mi++) {                                    \
                const int ra = warp_m * 64 + mi * 16 + grp;                     \
                af[mi][0] = __float_as_uint(ab[SW_WORD(ra,     kb + tig    )]); \
                af[mi][1] = __float_as_uint(ab[SW_WORD(ra + 8, kb + tig    )]); \
                af[mi][2] = __float_as_uint(ab[SW_WORD(ra,     kb + tig + 4)]); \
                af[mi][3] = __float_as_uint(ab[SW_WORD(ra + 8, kb + tig + 4)]); \
            }                                                                   \
            _Pragma("unroll")                                                   \
            for (int nj = 0; nj < 4; nj++) {                                    \
                const int nb = warp_n * 32 + nj * 8 + grp;                      \
                bf[nj][0] = __float_as_uint(bbs[SW_WORD(nb, kb + tig    )]);    \
                bf[nj][1] = __float_as_uint(bbs[SW_WORD(nb, kb + tig + 4)]);    \
            }                                                                   \
            _Pragma("unroll")                                                   \
            for (int mi = 0; mi < 4; mi++)                                      \
                _Pragma("unroll")                                               \
                for (int nj = 0; nj < 4; nj++)                                  \
                    mma_tf32(acc[mi][nj], af[mi], bf[nj]);                      \
        }                                                                       \
    }

    const int S = SS >> 4;   // 128 stages

    ISSUE_BODY(0, 0)   CP_COMMIT();
    ISSUE_BODY(1, 16)  CP_COMMIT();
    ISSUE_BODY(2, 32)  CP_COMMIT();

    for (int s = 0; s < S; s++) {
        CP_WAIT2();
        __syncthreads();
        TRANSFORM(s & 3, s * 16)
        __syncthreads();
        COMPUTE(s & 3)
        if (s + 3 < S) {
            ISSUE_BODY((s + 3) & 3, (s + 3) * 16)
        }
        CP_COMMIT();
    }

    // ---- write ctx (tf32-rounded: feeds out-projection) ----
#pragma unroll
    for (int nj = 0; nj < 4; nj++) {
        const int cc = warp_n * 32 + nj * 8 + tig * 2;
#pragma unroll
        for (int mi = 0; mi < 4; mi++) {
            const long long r0 = m0 + warp_m * 64 + mi * 16 + grp;
            const long long r1 = r0 + 8;
            float2 v0, v1;
            v0.x = rnd_tf32(acc[mi][nj][0]);
            v0.y = rnd_tf32(acc[mi][nj][1]);
            v1.x = rnd_tf32(acc[mi][nj][2]);
            v1.y = rnd_tf32(acc[mi][nj][3]);
            *reinterpret_cast<float2*>(C + r0 * DMODEL + cc) = v0;
            *reinterpret_cast<float2*>(C + r1 * DMODEL + cc) = v1;
        }
    }
#undef ISSUE_BODY
#undef TRANSFORM
#undef COMPUTE
}

// ----------------------------------------------------------------------------
// V transpose: g_v [(b*S+s)][h*128+n]  ->  g_vt [((b*8+h)*128+n)][s]
// ----------------------------------------------------------------------------
__global__ void transpose_v_kernel(const float* __restrict__ v, float* __restrict__ vt)
{
    __shared__ float t[32][33];
    const int z = blockIdx.z, b = z >> 3, h = z & 7;
    const int s0 = blockIdx.x * 32, n0 = blockIdx.y * 32;
    const int tx = threadIdx.x, ty = threadIdx.y;
#pragma unroll
    for (int j = ty; j < 32; j += 8)
        t[j][tx] = v[((long long)b * SS + s0 + j) * DMODEL + h * DK + n0 + tx];
    __syncthreads();
#pragma unroll
    for (int j = ty; j < 32; j += 8)
        vt[((long long)z * DK + n0 + j) * SS + s0 + tx] = t[tx][j];
}

extern "C" void kernel_launch(void* const* d_in, const int* in_sizes, int n_in,
                              void* d_out, int out_size)
{
    const float* Q  = (const float*)d_in[0];
    const float* K  = (const float*)d_in[1];
    const float* V  = (const float*)d_in[2];
    const float* Wq = (const float*)d_in[3];
    const float* bq = (const float*)d_in[4];
    const float* Wk = (const float*)d_in[5];
    const float* bk = (const float*)d_in[6];
    const float* Wv = (const float*)d_in[7];
    const float* bv = (const float*)d_in[8];
    const float* Wo = (const float*)d_in[9];
    const float* bo = (const float*)d_in[10];

    float* out = (float*)d_out;

    const long long OUT_ELEMS  = (long long)BB * SS * DMODEL;
    const long long ATTN_ELEMS = (long long)NZ * SS * SS;

    float *qp, *kp, *vp, *vtp, *ctxp, *rawp, *sMp, *sSp, *rMp, *rIp, *wp;
    cudaGetSymbolAddress((void**)&qp,   g_q);
    cudaGetSymbolAddress((void**)&kp,   g_k);
    cudaGetSymbolAddress((void**)&vp,   g_v);
    cudaGetSymbolAddress((void**)&vtp,  g_vt);
    cudaGetSymbolAddress((void**)&ctxp, g_ctx);
    cudaGetSymbolAddress((void**)&rawp, g_raw);
    cudaGetSymbolAddress((void**)&sMp,  g_statsM);
    cudaGetSymbolAddress((void**)&sSp,  g_statsS);
    cudaGetSymbolAddress((void**)&rMp,  g_rowM);
    cudaGetSymbolAddress((void**)&rIp,  g_rowInv);
    cudaGetSymbolAddress((void**)&wp,   g_w);

    float* attn = ((long long)out_size >= OUT_ELEMS + ATTN_ELEMS)
                      ? (out + OUT_ELEMS) : rawp;

    // GEMM variants: <HAS_BIAS, STATS, CVT_A, CVT_B, ROUND_OUT>
    auto projK  = gemm_cp_kernel<true,  false, true,  false, true >;
    auto scoreK = gemm_cp_kernel<false, true,  false, false, false>;
    auto outK   = gemm_cp_kernel<true,  false, false, false, false>;
    cudaFuncSetAttribute(projK,  cudaFuncAttributeMaxDynamicSharedMemorySize, GEMM_SMEM_BYTES);
    cudaFuncSetAttribute(scoreK, cudaFuncAttributeMaxDynamicSharedMemorySize, GEMM_SMEM_BYTES);
    cudaFuncSetAttribute(outK,   cudaFuncAttributeMaxDynamicSharedMemorySize, GEMM_SMEM_BYTES);
    cudaFuncSetAttribute(ctx_fused_kernel,
                         cudaFuncAttributeMaxDynamicSharedMemorySize, CTX_SMEM_BYTES);

    const int M = BB * SS;
    const float inv_sqrt_dk = 0.08838834764831845f;

    dim3 blk(256);

    // 0) prepass: round weights to tf32 (order: Wq, Wk, Wv, Wo)
    {
        dim3 gW(DMODEL * DMODEL / (256 * 4), 1, 4);
        round_weights_kernel<<<gW, blk>>>(Wq, Wk, Wv, Wo, wp);
    }
    float* wq = wp;
    float* wk = wp + (size_t)DMODEL * DMODEL;
    float* wv = wp + 2 * (size_t)DMODEL * DMODEL;
    float* wo = wp + 3 * (size_t)DMODEL * DMODEL;

    // 1-3) projections: X @ W^T + b (outputs tf32-rounded)
    dim3 gProj(DMODEL / 128, M / 128, 1);
    projK<<<gProj, blk, GEMM_SMEM_BYTES>>>(Q, wq, bq, qp,
        DMODEL, DMODEL, DMODEL, DMODEL, 1.0f, 1, 0, 0, 0, 0, 0, 0, nullptr, nullptr);
    projK<<<gProj, blk, GEMM_SMEM_BYTES>>>(K, wk, bk, kp,
        DMODEL, DMODEL, DMODEL, DMODEL, 1.0f, 1, 0, 0, 0, 0, 0, 0, nullptr, nullptr);
    projK<<<gProj, blk, GEMM_SMEM_BYTES>>>(V, wv, bv, vp,
        DMODEL, DMODEL, DMODEL, DMODEL, 1.0f, 1, 0, 0, 0, 0, 0, 0, nullptr, nullptr);

    // 3b) transpose V per head (values already tf32-rounded)
    {
        dim3 gT(SS / 32, DK / 32, NZ);
        dim3 bT(32, 8);
        transpose_v_kernel<<<gT, bT>>>(vp, vtp);
    }

    // 4) raw scores = q @ k^T / sqrt(dk), with per-tile softmax stats (cvt-free)
    dim3 gScores(SS / 128, SS / 128, NZ);
    scoreK<<<gScores, blk, GEMM_SMEM_BYTES>>>(qp, kp, nullptr, rawp,
        DK, DMODEL, DMODEL, SS, inv_sqrt_dk,
        NHEADS,
        (long long)SS * DMODEL, (long long)DK,
        (long long)SS * DMODEL, (long long)DK,
        (long long)NHEADS * SS * SS, (long long)SS * SS,
        sMp, sSp);

    // 5) combine stats -> rowM, rowInv
    combine_stats_kernel<<<(NZ * SS) / 256, blk>>>(sMp, sSp, rMp, rIp);

    // 6) fused softmax + ctx GEMM (+ attn output write), cvt-free fragments
    {
        dim3 gCtx(1, SS / 128, NZ);
        ctx_fused_kernel<<<gCtx, blk, CTX_SMEM_BYTES>>>(rawp, vtp, ctxp, attn, rMp, rIp);
    }

    // 7) out = ctx @ Wo^T + bo (cvt-free)
    outK<<<gProj, blk, GEMM_SMEM_BYTES>>>(ctxp, wo, bo, out,
        DMODEL, DMODEL, DMODEL, DMODEL, 1.0f, 1, 0, 0, 0, 0, 0, 0, nullptr, nullptr);
}

// round 9
// speedup vs baseline: 3.6012x; 1.0555x over previous
#include <cuda_runtime.h>
#include <math.h>
#include <stdint.h>

#define DMODEL 1024
#define NHEADS 8
#define DK 128
#define BB 2
#define SS 2048
#define NZ (BB * NHEADS)          // 16
#define NTILE (SS / 128)          // 16

// Scratch (allocation-free rule: __device__ globals)
__device__ float g_q[(size_t)BB * SS * DMODEL];
__device__ float g_k[(size_t)BB * SS * DMODEL];
__device__ float g_v[(size_t)BB * SS * DMODEL];
__device__ float g_vt[(size_t)BB * NHEADS * DK * SS];
__device__ float g_ctx[(size_t)BB * SS * DMODEL];
__device__ float g_raw[(size_t)NZ * SS * SS];
__device__ float g_statsM[(size_t)NZ * SS * NTILE];
__device__ float g_statsS[(size_t)NZ * SS * NTILE];
__device__ float g_rowM[(size_t)NZ * SS];
__device__ float g_rowInv[(size_t)NZ * SS];
__device__ float g_w[4][(size_t)DMODEL * DMODEL];

__device__ __forceinline__ uint32_t smem_u32(const void* p) {
    uint32_t a;
    asm("{ .reg .u64 t; cvta.to.shared.u64 t, %1; cvt.u32.u64 %0, t; }" : "=r"(a) : "l"(p));
    return a;
}
__device__ __forceinline__ uint32_t f2tf32(float f) {
    uint32_t u;
    asm("cvt.rna.tf32.f32 %0, %1;" : "=r"(u) : "f"(f));
    return u;
}
__device__ __forceinline__ uint32_t f2tf32_u(uint32_t x) {
    return f2tf32(__uint_as_float(x));
}
__device__ __forceinline__ float rnd_tf32(float f) {
    return __uint_as_float(f2tf32(f));
}
__device__ __forceinline__ void mma_tf32(float* c, const uint32_t* a, const uint32_t* b) {
    asm volatile(
        "mma.sync.aligned.m16n8k8.row.col.f32.tf32.tf32.f32 "
        "{%0,%1,%2,%3},{%4,%5,%6,%7},{%8,%9},{%0,%1,%2,%3};"
        : "+f"(c[0]), "+f"(c[1]), "+f"(c[2]), "+f"(c[3])
        : "r"(a[0]), "r"(a[1]), "r"(a[2]), "r"(a[3]), "r"(b[0]), "r"(b[1]));
}
__device__ __forceinline__ void ldmatrix_x4(uint32_t* r, uint32_t addr) {
    asm volatile("ldmatrix.sync.aligned.m8n8.x4.shared.b16 {%0,%1,%2,%3}, [%4];"
                 : "=r"(r[0]), "=r"(r[1]), "=r"(r[2]), "=r"(r[3]) : "r"(addr));
}
__device__ __forceinline__ void ldmatrix_x2(uint32_t* r, uint32_t addr) {
    asm volatile("ldmatrix.sync.aligned.m8n8.x2.shared.b16 {%0,%1}, [%2];"
                 : "=r"(r[0]), "=r"(r[1]) : "r"(addr));
}
__device__ __forceinline__ void cp_async16(uint32_t saddr, const void* gaddr) {
    asm volatile("cp.async.cg.shared.global [%0], [%1], 16;"
                 :: "r"(saddr), "l"(gaddr) : "memory");
}
#define CP_COMMIT() asm volatile("cp.async.commit_group;" ::: "memory")
#define CP_WAIT2()  asm volatile("cp.async.wait_group 2;" ::: "memory")

// smem word index for (row m, k-word k) within a 128x16-word operand tile.
// XOR swizzle: conflict-free for 16B cp.async stores, and for ldmatrix the 8
// row-segments of each 8x8 matrix land on all 32 banks exactly once.
#define SW_WORD(m, k) ((uint32_t)(m) * 16u + ((uint32_t)(k) ^ (((((uint32_t)(m)) >> 1) & 3u) << 2)))

#define STAGE_BYTES 16384u
#define GEMM_SMEM_BYTES 65536u
#define CTX_SMEM_BYTES 66560u

// Per-thread ldmatrix address prep (shared by both GEMM kernels).
// A x4: lane -> (mat = lane>>3 within {row+0/+8 x kseg/kseg+1}), row = base+ (lane&7)
// B x2: lanes 0..15 -> 2 matrices (kseg, kseg+1); lanes 16+ replicate.
#define LDM_PREP()                                                              \
    uint32_t aBaseW[4], aXorW[4];                                               \
    _Pragma("unroll")                                                           \
    for (int mi = 0; mi < 4; mi++) {                                            \
        const int rowa = warp_m * 64 + mi * 16 + (lane & 7) + ((lane >> 3) & 1) * 8; \
        aBaseW[mi] = (uint32_t)rowa * 16u;                                      \
        aXorW[mi]  = (((uint32_t)rowa >> 1) & 3u) << 2;                         \
    }                                                                           \
    const uint32_t aKsel = ((uint32_t)lane >> 4) * 4u;                          \
    uint32_t bBaseW[4], bXorW[4];                                               \
    _Pragma("unroll")                                                           \
    for (int nj = 0; nj < 4; nj++) {                                            \
        const int rowb = warp_n * 32 + nj * 8 + (lane & 7);                     \
        bBaseW[nj] = (uint32_t)rowb * 16u;                                      \
        bXorW[nj]  = (((uint32_t)rowb >> 1) & 3u) << 2;                         \
    }                                                                           \
    const uint32_t bKsel = (((uint32_t)lane >> 3) & 1u) * 4u;

// ============================================================================
// Generic batched TF32 GEMM (cp.async 4-stage, ldmatrix fragments)
//   C = alpha * A @ B^T + bias
// ============================================================================
template <bool HAS_BIAS, bool STATS, bool CVT_A, bool CVT_B, bool ROUND_OUT>
__global__ __launch_bounds__(256, 2) void gemm_cp_kernel(
    const float* __restrict__ A, const float* __restrict__ B,
    const float* __restrict__ bias, float* __restrict__ C,
    int K, int lda, int ldb, int ldc, float alpha,
    int Hdiv,
    long long sAb, long long sAh,
    long long sBb, long long sBh,
    long long sCb, long long sCh,
    float* __restrict__ statsM, float* __restrict__ statsS)
{
    extern __shared__ char smem[];
    const uint32_t sb = smem_u32(smem);

    const int z  = blockIdx.z;
    const int zb = z / Hdiv;
    const int zh = z % Hdiv;
    A += zb * sAb + zh * sAh;
    B += zb * sBb + zh * sBh;
    C += zb * sCb + zh * sCh;

    const int tid  = threadIdx.x;
    const int wid  = tid >> 5;
    const int lane = tid & 31;
    const int m0   = blockIdx.y * 128;
    const int n0   = blockIdx.x * 128;
    const int warp_m = wid >> 2;
    const int warp_n = wid & 3;
    const int grp  = lane >> 2;
    const int tig  = lane & 3;

    const int lm = tid >> 2;
    const int lc = (tid & 3) * 4;

    LDM_PREP()

    float acc[4][4][4];
#pragma unroll
    for (int i = 0; i < 4; i++)
#pragma unroll
        for (int j = 0; j < 4; j++)
#pragma unroll
            for (int q = 0; q < 4; q++) acc[i][j][q] = 0.0f;

#define ISSUE_BODY(bufi, k0)                                                    \
    {                                                                           \
        const uint32_t ab = sb + (uint32_t)(bufi) * STAGE_BYTES;                \
        const uint32_t bbs = ab + 8192u;                                        \
        _Pragma("unroll")                                                       \
        for (int i = 0; i < 2; i++) {                                           \
            const int m = lm + i * 64;                                          \
            cp_async16(ab + SW_WORD(m, lc) * 4u,                                \
                       A + (long long)(m0 + m) * lda + (k0) + lc);              \
            cp_async16(bbs + SW_WORD(m, lc) * 4u,                               \
                       B + (long long)(n0 + m) * ldb + (k0) + lc);              \
        }                                                                       \
    }

#define COMPUTE(bufi)                                                           \
    {                                                                           \
        const uint32_t abuf = sb + (uint32_t)(bufi) * STAGE_BYTES;              \
        const uint32_t bbuf = abuf + 8192u;                                     \
        _Pragma("unroll")                                                       \
        for (int ks = 0; ks < 2; ks++) {                                        \
            const uint32_t kb = ks * 8;                                         \
            uint32_t af[4][4], bf[4][2];                                        \
            _Pragma("unroll")                                                   \
            for (int mi = 0; mi < 4; mi++) {                                    \
                const uint32_t kw = kb + aKsel;                                 \
                ldmatrix_x4(af[mi], abuf + (aBaseW[mi] + (kw ^ aXorW[mi])) * 4u); \
                if (CVT_A) {                                                    \
                    af[mi][0] = f2tf32_u(af[mi][0]);                            \
                    af[mi][1] = f2tf32_u(af[mi][1]);                            \
                    af[mi][2] = f2tf32_u(af[mi][2]);                            \
                    af[mi][3] = f2tf32_u(af[mi][3]);                            \
                }                                                               \
            }                                                                   \
            _Pragma("unroll")                                                   \
            for (int nj = 0; nj < 4; nj++) {                                    \
                const uint32_t kw = kb + bKsel;                                 \
                ldmatrix_x2(bf[nj], bbuf + (bBaseW[nj] + (kw ^ bXorW[nj])) * 4u); \
                if (CVT_B) {                                                    \
                    bf[nj][0] = f2tf32_u(bf[nj][0]);                            \
                    bf[nj][1] = f2tf32_u(bf[nj][1]);                            \
                }                                                               \
            }                                                                   \
            _Pragma("unroll")                                                   \
            for (int mi = 0; mi < 4; mi++)                                      \
                _Pragma("unroll")                                               \
                for (int nj = 0; nj < 4; nj++)                                  \
                    mma_tf32(acc[mi][nj], af[mi], bf[nj]);                      \
        }                                                                       \
    }

    const int S = K >> 4;

    ISSUE_BODY(0, 0)   CP_COMMIT();
    ISSUE_BODY(1, 16)  CP_COMMIT();
    ISSUE_BODY(2, 32)  CP_COMMIT();

    for (int s = 0; s < S; s++) {
        CP_WAIT2();
        __syncthreads();
        COMPUTE(s & 3)
        if (s + 3 < S) {
            ISSUE_BODY((s + 3) & 3, (s + 3) * 16)
        }
        CP_COMMIT();   // unconditional: exact wait_group accounting in the tail
    }

    // ---- write C ----
#pragma unroll
    for (int nj = 0; nj < 4; nj++) {
        const int cc = n0 + warp_n * 32 + nj * 8 + tig * 2;
        float b0 = 0.0f, b1 = 0.0f;
        if (HAS_BIAS) { b0 = bias[cc]; b1 = bias[cc + 1]; }
#pragma unroll
        for (int mi = 0; mi < 4; mi++) {
            const long long r0 = m0 + warp_m * 64 + mi * 16 + grp;
            const long long r1 = r0 + 8;
            float2 v0, v1;
            v0.x = alpha * acc[mi][nj][0] + b0;
            v0.y = alpha * acc[mi][nj][1] + b1;
            v1.x = alpha * acc[mi][nj][2] + b0;
            v1.y = alpha * acc[mi][nj][3] + b1;
            if (ROUND_OUT) {
                v0.x = rnd_tf32(v0.x); v0.y = rnd_tf32(v0.y);
                v1.x = rnd_tf32(v1.x); v1.y = rnd_tf32(v1.y);
            }
            *reinterpret_cast<float2*>(C + r0 * ldc + cc) = v0;
            *reinterpret_cast<float2*>(C + r1 * ldc + cc) = v1;
        }
    }

    // ---- per-tile softmax stats (scores only) ----
    if (STATS) {
        __syncthreads();
        float* sred    = reinterpret_cast<float*>(smem);          // [4][128]
        float* rowmaxs = reinterpret_cast<float*>(smem) + 512;    // [128]

#pragma unroll
        for (int mi = 0; mi < 4; mi++) {
#pragma unroll
            for (int h = 0; h < 2; h++) {
                float mx = -1e30f;
#pragma unroll
                for (int nj = 0; nj < 4; nj++)
                    mx = fmaxf(mx, fmaxf(alpha * acc[mi][nj][h * 2],
                                         alpha * acc[mi][nj][h * 2 + 1]));
                mx = fmaxf(mx, __shfl_xor_sync(0xffffffffu, mx, 1));
                mx = fmaxf(mx, __shfl_xor_sync(0xffffffffu, mx, 2));
                const int rl = warp_m * 64 + mi * 16 + grp + h * 8;
                if (tig == 0) sred[warp_n * 128 + rl] = mx;
            }
        }
        __syncthreads();
        if (tid < 128) {
            float rm = fmaxf(fmaxf(sred[tid], sred[128 + tid]),
                             fmaxf(sred[256 + tid], sred[384 + tid]));
            rowmaxs[tid] = rm;
        }
        __syncthreads();

#pragma unroll
        for (int mi = 0; mi < 4; mi++) {
#pragma unroll
            for (int h = 0; h < 2; h++) {
                const int rl = warp_m * 64 + mi * 16 + grp + h * 8;
                const float rm = rowmaxs[rl];
                float s = 0.0f;
#pragma unroll
                for (int nj = 0; nj < 4; nj++) {
                    s += __expf(alpha * acc[mi][nj][h * 2]     - rm);
                    s += __expf(alpha * acc[mi][nj][h * 2 + 1] - rm);
                }
                s += __shfl_xor_sync(0xffffffffu, s, 1);
                s += __shfl_xor_sync(0xffffffffu, s, 2);
                if (tig == 0) sred[warp_n * 128 + rl] = s;
            }
        }
        __syncthreads();
        if (tid < 128) {
            const float sg = sred[tid] + sred[128 + tid] + sred[256 + tid] + sred[384 + tid];
            const long long gi = ((long long)z * SS + m0 + tid) * NTILE + blockIdx.x;
            statsM[gi] = rowmaxs[tid];
            statsS[gi] = sg;
        }
    }
#undef ISSUE_BODY
#undef COMPUTE
}

// ============================================================================
// Round weight matrices to tf32 (prepass). grid.z selects the matrix.
// ============================================================================
__global__ __launch_bounds__(256) void round_weights_kernel(
    const float* __restrict__ w0, const float* __restrict__ w1,
    const float* __restrict__ w2, const float* __restrict__ w3,
    float* __restrict__ dst)
{
    const float* src = (blockIdx.z == 0) ? w0 : (blockIdx.z == 1) ? w1
                     : (blockIdx.z == 2) ? w2 : w3;
    float* d = dst + (size_t)blockIdx.z * DMODEL * DMODEL;
    const long long i = ((long long)blockIdx.x * 256 + threadIdx.x) * 4;
    float4 v = *reinterpret_cast<const float4*>(src + i);
    v.x = rnd_tf32(v.x); v.y = rnd_tf32(v.y);
    v.z = rnd_tf32(v.z); v.w = rnd_tf32(v.w);
    *reinterpret_cast<float4*>(d + i) = v;
}

// ============================================================================
// Combine per-tile stats into global row max + inverse sum.
// ============================================================================
__global__ __launch_bounds__(256) void combine_stats_kernel(
    const float* __restrict__ sM, const float* __restrict__ sS,
    float* __restrict__ rowM, float* __restrict__ rowInv)
{
    const long long r = (long long)blockIdx.x * 256 + threadIdx.x;
    const float* pm = sM + r * NTILE;
    const float* ps = sS + r * NTILE;
    float M = -1e30f;
#pragma unroll
    for (int t = 0; t < NTILE; t++) M = fmaxf(M, pm[t]);
    float S = 0.0f;
#pragma unroll
    for (int t = 0; t < NTILE; t++) S += ps[t] * __expf(pm[t] - M);
    rowM[r]   = M;
    rowInv[r] = 1.0f / S;
}

// ============================================================================
// Fused softmax + ctx GEMM (ldmatrix fragments, cvt-free).
// ============================================================================
__global__ __launch_bounds__(256, 2) void ctx_fused_kernel(
    const float* __restrict__ RAW, const float* __restrict__ VT,
    float* __restrict__ CTX, float* __restrict__ ATTN,
    const float* __restrict__ rowM, const float* __restrict__ rowInv)
{
    extern __shared__ char smem[];
    const uint32_t sb = smem_u32(smem);
    float* sM_s = reinterpret_cast<float*>(smem + GEMM_SMEM_BYTES);
    float* sI_s = sM_s + 128;

    const int z  = blockIdx.z;
    const int zb = z >> 3;
    const int zh = z & 7;
    const float* A = RAW + (long long)z * SS * SS;
    const float* B = VT + (long long)z * DK * SS;
    float* C = CTX + (long long)zb * SS * DMODEL + (long long)zh * DK;
    float* AT = ATTN + (long long)z * SS * SS;

    const int tid  = threadIdx.x;
    const int wid  = tid >> 5;
    const int lane = tid & 31;
    const int m0   = blockIdx.y * 128;
    const int warp_m = wid >> 2;
    const int warp_n = wid & 3;
    const int grp  = lane >> 2;
    const int tig  = lane & 3;

    const int lm = tid >> 2;
    const int lc = (tid & 3) * 4;

    LDM_PREP()

    if (tid < 128) {
        sM_s[tid] = rowM[(long long)z * SS + m0 + tid];
        sI_s[tid] = rowInv[(long long)z * SS + m0 + tid];
    }

    float acc[4][4][4];
#pragma unroll
    for (int i = 0; i < 4; i++)
#pragma unroll
        for (int j = 0; j < 4; j++)
#pragma unroll
            for (int q = 0; q < 4; q++) acc[i][j][q] = 0.0f;

#define ISSUE_BODY(bufi, k0)                                                    \
    {                                                                           \
        const uint32_t ab = sb + (uint32_t)(bufi) * STAGE_BYTES;                \
        const uint32_t bbs = ab + 8192u;                                        \
        _Pragma("unroll")                                                       \
        for (int i = 0; i < 2; i++) {                                           \
            const int m = lm + i * 64;                                          \
            cp_async16(ab + SW_WORD(m, lc) * 4u,                                \
                       A + (long long)(m0 + m) * SS + (k0) + lc);               \
            cp_async16(bbs + SW_WORD(m, lc) * 4u,                               \
                       B + (long long)m * SS + (k0) + lc);                      \
        }                                                                       \
    }

#define TRANSFORM(bufi, k0)                                                     \
    {                                                                           \
        float* ab = reinterpret_cast<float*>(smem + (uint32_t)(bufi) * STAGE_BYTES); \
        _Pragma("unroll")                                                       \
        for (int i = 0; i < 2; i++) {                                           \
            const int m = (tid >> 2) + i * 64;                                  \
            const int kg = (tid & 3) * 4;                                       \
            const float rm = sM_s[m], ri = sI_s[m];                             \
            float4* p = reinterpret_cast<float4*>(&ab[SW_WORD(m, kg)]);         \
            float4 v = *p;                                                      \
            v.x = __expf(v.x - rm) * ri;                                        \
            v.y = __expf(v.y - rm) * ri;                                        \
            v.z = __expf(v.z - rm) * ri;                                        \
            v.w = __expf(v.w - rm) * ri;                                        \
            *reinterpret_cast<float4*>(AT + (long long)(m0 + m) * SS + (k0) + kg) = v; \
            float4 r4;                                                          \
            r4.x = rnd_tf32(v.x); r4.y = rnd_tf32(v.y);                         \
            r4.z = rnd_tf32(v.z); r4.w = rnd_tf32(v.w);                         \
            *p = r4;                                                            \
        }                                                                       \
    }

#define COMPUTE(bufi)                                                           \
    {                                                                           \
        const uint32_t abuf = sb + (uint32_t)(bufi) * STAGE_BYTES;              \
        const uint32_t bbuf = abuf + 8192u;                                     \
        _Pragma("unroll")                                                       \
        for (int ks = 0; ks < 2; ks++) {                                        \
            const uint32_t kb = ks * 8;                                         \
            uint32_t af[4][4], bf[4][2];                                        \
            _Pragma("unroll")                                                   \
            for (int mi = 0; mi < 4; mi++) {                                    \
                const uint32_t kw = kb + aKsel;                                 \
                ldmatrix_x4(af[mi], abuf + (aBaseW[mi] + (kw ^ aXorW[mi])) * 4u); \
            }                                                                   \
            _Pragma("unroll")                                                   \
            for (int nj = 0; nj < 4; nj++) {                                    \
                const uint32_t kw = kb + bKsel;                                 \
                ldmatrix_x2(bf[nj], bbuf + (bBaseW[nj] + (kw ^ bXorW[nj])) * 4u); \
            }                                                                   \
            _Pragma("unroll")                                                   \
            for (int mi = 0; mi < 4; mi++)                                      \
                _Pragma("unroll")                                               \
                for (int nj = 0; nj < 4; nj++)                                  \
                    mma_tf32(acc[mi][nj], af[mi], bf[nj]);                      \
        }                                                                       \
    }

    const int S = SS >> 4;   // 128 stages

    ISSUE_BODY(0, 0)   CP_COMMIT();
    ISSUE_BODY(1, 16)  CP_COMMIT();
    ISSUE_BODY(2, 32)  CP_COMMIT();

    for (int s = 0; s < S; s++) {
        CP_WAIT2();
        __syncthreads();
        TRANSFORM(s & 3, s * 16)
        __syncthreads();
        COMPUTE(s & 3)
        if (s + 3 < S) {
            ISSUE_BODY((s + 3) & 3, (s + 3) * 16)
        }
        CP_COMMIT();
    }

    // ---- write ctx (tf32-rounded: feeds out-projection) ----
#pragma unroll
    for (int nj = 0; nj < 4; nj++) {
        const int cc = warp_n * 32 + nj * 8 + tig * 2;
#pragma unroll
        for (int mi = 0; mi < 4; mi++) {
            const long long r0 = m0 + warp_m * 64 + mi * 16 + grp;
            const long long r1 = r0 + 8;
            float2 v0, v1;
            v0.x = rnd_tf32(acc[mi][nj][0]);
            v0.y = rnd_tf32(acc[mi][nj][1]);
            v1.x = rnd_tf32(acc[mi][nj][2]);
            v1.y = rnd_tf32(acc[mi][nj][3]);
            *reinterpret_cast<float2*>(C + r0 * DMODEL + cc) = v0;
            *reinterpret_cast<float2*>(C + r1 * DMODEL + cc) = v1;
        }
    }
#undef ISSUE_BODY
#undef TRANSFORM
#undef COMPUTE
}

// ----------------------------------------------------------------------------
// V transpose: g_v [(b*S+s)][h*128+n]  ->  g_vt [((b*8+h)*128+n)][s]
// ----------------------------------------------------------------------------
__global__ void transpose_v_kernel(const float* __restrict__ v, float* __restrict__ vt)
{
    __shared__ float t[32][33];
    const int z = blockIdx.z, b = z >> 3, h = z & 7;
    const int s0 = blockIdx.x * 32, n0 = blockIdx.y * 32;
    const int tx = threadIdx.x, ty = threadIdx.y;
#pragma unroll
    for (int j = ty; j < 32; j += 8)
        t[j][tx] = v[((long long)b * SS + s0 + j) * DMODEL + h * DK + n0 + tx];
    __syncthreads();
#pragma unroll
    for (int j = ty; j < 32; j += 8)
        vt[((long long)z * DK + n0 + j) * SS + s0 + tx] = t[tx][j];
}

extern "C" void kernel_launch(void* const* d_in, const int* in_sizes, int n_in,
                              void* d_out, int out_size)
{
    const float* Q  = (const float*)d_in[0];
    const float* K  = (const float*)d_in[1];
    const float* V  = (const float*)d_in[2];
    const float* Wq = (const float*)d_in[3];
    const float* bq = (const float*)d_in[4];
    const float* Wk = (const float*)d_in[5];
    const float* bk = (const float*)d_in[6];
    const float* Wv = (const float*)d_in[7];
    const float* bv = (const float*)d_in[8];
    const float* Wo = (const float*)d_in[9];
    const float* bo = (const float*)d_in[10];

    float* out = (float*)d_out;

    const long long OUT_ELEMS  = (long long)BB * SS * DMODEL;
    const long long ATTN_ELEMS = (long long)NZ * SS * SS;

    float *qp, *kp, *vp, *vtp, *ctxp, *rawp, *sMp, *sSp, *rMp, *rIp, *wp;
    cudaGetSymbolAddress((void**)&qp,   g_q);
    cudaGetSymbolAddress((void**)&kp,   g_k);
    cudaGetSymbolAddress((void**)&vp,   g_v);
    cudaGetSymbolAddress((void**)&vtp,  g_vt);
    cudaGetSymbolAddress((void**)&ctxp, g_ctx);
    cudaGetSymbolAddress((void**)&rawp, g_raw);
    cudaGetSymbolAddress((void**)&sMp,  g_statsM);
    cudaGetSymbolAddress((void**)&sSp,  g_statsS);
    cudaGetSymbolAddress((void**)&rMp,  g_rowM);
    cudaGetSymbolAddress((void**)&rIp,  g_rowInv);
    cudaGetSymbolAddress((void**)&wp,   g_w);

    float* attn = ((long long)out_size >= OUT_ELEMS + ATTN_ELEMS)
                      ? (out + OUT_ELEMS) : rawp;

    auto projK  = gemm_cp_kernel<true,  false, true,  false, true >;
    auto scoreK = gemm_cp_kernel<false, true,  false, false, false>;
    auto outK   = gemm_cp_kernel<true,  false, false, false, false>;
    cudaFuncSetAttribute(projK,  cudaFuncAttributeMaxDynamicSharedMemorySize, GEMM_SMEM_BYTES);
    cudaFuncSetAttribute(scoreK, cudaFuncAttributeMaxDynamicSharedMemorySize, GEMM_SMEM_BYTES);
    cudaFuncSetAttribute(outK,   cudaFuncAttributeMaxDynamicSharedMemorySize, GEMM_SMEM_BYTES);
    cudaFuncSetAttribute(ctx_fused_kernel,
                         cudaFuncAttributeMaxDynamicSharedMemorySize, CTX_SMEM_BYTES);

    const int M = BB * SS;
    const float inv_sqrt_dk = 0.08838834764831845f;

    dim3 blk(256);

    // 0) prepass: round weights to tf32
    {
        dim3 gW(DMODEL * DMODEL / (256 * 4), 1, 4);
        round_weights_kernel<<<gW, blk>>>(Wq, Wk, Wv, Wo, wp);
    }
    float* wq = wp;
    float* wk = wp + (size_t)DMODEL * DMODEL;
    float* wv = wp + 2 * (size_t)DMODEL * DMODEL;
    float* wo = wp + 3 * (size_t)DMODEL * DMODEL;

    // 1-3) projections: X @ W^T + b (outputs tf32-rounded)
    dim3 gProj(DMODEL / 128, M / 128, 1);
    projK<<<gProj, blk, GEMM_SMEM_BYTES>>>(Q, wq, bq, qp,
        DMODEL, DMODEL, DMODEL, DMODEL, 1.0f, 1, 0, 0, 0, 0, 0, 0, nullptr, nullptr);
    projK<<<gProj, blk, GEMM_SMEM_BYTES>>>(K, wk, bk, kp,
        DMODEL, DMODEL, DMODEL, DMODEL, 1.0f, 1, 0, 0, 0, 0, 0, 0, nullptr, nullptr);
    projK<<<gProj, blk, GEMM_SMEM_BYTES>>>(V, wv, bv, vp,
        DMODEL, DMODEL, DMODEL, DMODEL, 1.0f, 1, 0, 0, 0, 0, 0, 0, nullptr, nullptr);

    // 3b) transpose V per head
    {
        dim3 gT(SS / 32, DK / 32, NZ);
        dim3 bT(32, 8);
        transpose_v_kernel<<<gT, bT>>>(vp, vtp);
    }

    // 4) raw scores + per-tile softmax stats
    dim3 gScores(SS / 128, SS / 128, NZ);
    scoreK<<<gScores, blk, GEMM_SMEM_BYTES>>>(qp, kp, nullptr, rawp,
        DK, DMODEL, DMODEL, SS, inv_sqrt_dk,
        NHEADS,
        (long long)SS * DMODEL, (long long)DK,
        (long long)SS * DMODEL, (long long)DK,
        (long long)NHEADS * SS * SS, (long long)SS * SS,
        sMp, sSp);

    // 5) combine stats
    combine_stats_kernel<<<(NZ * SS) / 256, blk>>>(sMp, sSp, rMp, rIp);

    // 6) fused softmax + ctx GEMM (+ attn output write)
    {
        dim3 gCtx(1, SS / 128, NZ);
        ctx_fused_kernel<<<gCtx, blk, CTX_SMEM_BYTES>>>(rawp, vtp, ctxp, attn, rMp, rIp);
    }

    // 7) out = ctx @ Wo^T + bo
    outK<<<gProj, blk, GEMM_SMEM_BYTES>>>(ctxp, wo, bo, out,
        DMODEL, DMODEL, DMODEL, DMODEL, 1.0f, 1, 0, 0, 0, 0, 0, 0, nullptr, nullptr);
}